// round 12
// baseline (speedup 1.0000x reference)
#include <cuda_runtime.h>
#include <cuda_bf16.h>
#include <cuda_fp16.h>
#include <math.h>
#include <stdint.h>

// ---------------- problem constants ----------------
#define CKD 64
#define QD 1620          // H*W
#define MD 32400
#define TOPK 20
#define CHD 1536         // OD*CVD

// ---------------- filter tiling ----------------
#define QT 128           // q per block
#define MTILE 64         // m per iteration
#define NQB 13           // 13*128 = 1664 >= 1620
#define NCHUNK 22
#define CHUNKP 1536      // m per chunk
#define ITERS1 24        // CHUNKP / MTILE
#define MPAD (NCHUNK * CHUNKP)   // 33792
#define HCAP 512         // per-q hit capacity
#define NSTAGE 4
#define QT3 16

#define NAFF (NQB * NCHUNK)          // 286 GEMM blocks
#define TRX 507                      // ceil(MD/64) transpose m-blocks
#define TRY (CHD / 64)               // 24
#define NTR (TRX * TRY)              // 12168

// ---------------- device scratch ----------------
__device__ __align__(16) float g_nasq[MPAD];
__device__ __align__(16) __nv_bfloat16 g_mkt[(size_t)MPAD * CKD];
__device__ __align__(16) float g_mktf[(size_t)MD * CKD];
__device__ __align__(16) __half g_vth[(size_t)MD * CHD];
__device__ unsigned g_chunkmax[NQB * QT * NCHUNK];
__device__ int   g_hcnt[QD];
__device__ int   g_hits[(size_t)QD * HCAP];
__device__ float g_wval[QD * TOPK];
__device__ int   g_widx[QD * TOPK];

// order-preserving float<->uint map (unsigned domain)
__device__ __forceinline__ unsigned encf(float v) {
    unsigned b = __float_as_uint(v);
    return (b & 0x80000000u) ? ~b : (b | 0x80000000u);
}
__device__ __forceinline__ float decf(unsigned u) {
    unsigned b = (u & 0x80000000u) ? (u & 0x7FFFFFFFu) : ~u;
    return __uint_as_float(b);
}

// ---------------- async copy helpers ----------------
#define CP_ASYNC16(dst, src) \
    asm volatile("cp.async.cg.shared.global [%0], [%1], 16;" :: "r"(dst), "l"(src))
#define CP_COMMIT() asm volatile("cp.async.commit_group;")
#define CP_WAIT2()  asm volatile("cp.async.wait_group 2;" ::: "memory")

// ---------------- mma helper ----------------
__device__ __forceinline__ void mma_bf16(float* c, const uint32_t* a,
                                         uint32_t b0, uint32_t b1) {
    asm volatile(
        "mma.sync.aligned.m16n8k16.row.col.f32.bf16.bf16.f32 "
        "{%0,%1,%2,%3}, {%4,%5,%6,%7}, {%8,%9}, {%0,%1,%2,%3};"
        : "+f"(c[0]), "+f"(c[1]), "+f"(c[2]), "+f"(c[3])
        : "r"(a[0]), "r"(a[1]), "r"(a[2]), "r"(a[3]), "r"(b0), "r"(b1));
}

// ---------------- K0: prep — mk transpose (bf16+fp32) + nasq + hcnt zero -----
// grid MPAD/32 blocks, 256 threads; tile = full 64 c x 32 m
__global__ void __launch_bounds__(256) k_prep(const float* __restrict__ mk) {
    __shared__ float tile[CKD][33];
    const int m0 = blockIdx.x * 32;
    const int tid = threadIdx.x;

    // zero hit counters (first blocks)
    int gz = blockIdx.x * 256 + tid;
    if (gz < QD) g_hcnt[gz] = 0;

    // stage mk[c][m0..m0+31] for all 64 c
    {
        int ml = tid & 31;
        int m = m0 + ml;
        #pragma unroll
        for (int i = 0; i < 8; i++) {
            int c = (tid >> 5) + i * 8;
            tile[c][ml] = (m < MD) ? mk[(size_t)c * MD + m] : 0.f;
        }
    }
    __syncthreads();

    // write g_mkt bf16 + g_mktf fp32, [m][c]
    #pragma unroll
    for (int i = 0; i < 8; i++) {
        int idx = tid + i * 256;
        int ml = idx >> 6, c = idx & 63;
        float v = tile[c][ml];
        int m = m0 + ml;
        g_mkt[(size_t)m * CKD + c] = __float2bfloat16(v);
        if (m < MD) g_mktf[(size_t)m * CKD + c] = v;
    }

    // nasq: threads 0..31 reduce own column
    if (tid < 32) {
        int m = m0 + tid;
        float s = 0.f;
        #pragma unroll
        for (int c = 0; c < CKD; c++) {
            float v = tile[c][tid];
            s += v * v;
        }
        g_nasq[m] = (m < MD) ? -(s * 0.125f) : -1.0e37f;
    }
}

// ---------------- filter GEMM common smem layout (bytes) ----------------
#define SB_QKB   0                       // bf16 qk [128][68] = 17408
#define SB_B     17408                   // NSTAGE x (64 rows x 144B) = 36864
#define SB_NASQ  54272                   // NSTAGE x 256B = 1024
#define SB_RED   55296                   // 128 unsigned = 512
#define SB_TOTAL 55808

#define STAGE_B_ASYNC(s, mb) do { \
    const char* _gs = (const char*)g_mkt + (size_t)(mb) * (CKD * 2); \
    uint32_t _bb = sbase + SB_B + (s) * 9216; \
    _Pragma("unroll") \
    for (int _i = 0; _i < 2; _i++) { \
        int _idx = tid + _i * 256; \
        int _m = _idx >> 3, _c16 = _idx & 7; \
        CP_ASYNC16(_bb + _m * 144 + _c16 * 16, _gs + _m * 128 + _c16 * 16); \
    } \
    if (tid < 16) \
        CP_ASYNC16(sbase + SB_NASQ + (s) * 256 + tid * 16, \
                   (const char*)g_nasq + (size_t)(mb) * 4 + tid * 16); \
} while (0)

#define STAGE_QKB() do { \
    for (int t = tid; t < CKD * QT; t += 256) { \
        int c = t >> 7, j = t & 127; \
        int q = q0 + j; \
        float v = (q < QD) ? qk[c * QD + q] : 0.f; \
        qkb[j * 68 + c] = __float2bfloat16(v); \
    } \
} while (0)

#define LOAD_AFR() do { \
    _Pragma("unroll") \
    for (int Mt = 0; Mt < 2; Mt++) { \
        _Pragma("unroll") \
        for (int ks = 0; ks < 4; ks++) { \
            int qr = qw * 32 + Mt * 16 + r8; \
            int cc = ks * 16 + 2 * t4; \
            afr[Mt][ks][0] = *(const uint32_t*)&qkb[qr * 68 + cc]; \
            afr[Mt][ks][1] = *(const uint32_t*)&qkb[(qr + 8) * 68 + cc]; \
            afr[Mt][ks][2] = *(const uint32_t*)&qkb[qr * 68 + cc + 8]; \
            afr[Mt][ks][3] = *(const uint32_t*)&qkb[(qr + 8) * 68 + cc + 8]; \
        } \
    } \
} while (0)

#define DO_MMA(s) do { \
    const uint32_t* Bb = (const uint32_t*)(sm + SB_B + (s) * 9216); \
    _Pragma("unroll") \
    for (int ks = 0; ks < 4; ks++) { \
        _Pragma("unroll") \
        for (int Nt = 0; Nt < 4; Nt++) { \
            int nl = mw * 32 + Nt * 8 + r8; \
            uint32_t b0 = Bb[nl * 36 + ks * 8 + t4]; \
            uint32_t b1 = Bb[nl * 36 + ks * 8 + t4 + 4]; \
            mma_bf16(acc[0][Nt], afr[0][ks], b0, b1); \
            mma_bf16(acc[1][Nt], afr[1][ks], b0, b1); \
        } \
    } \
} while (0)

// ---------------- K1: FUSED  affA-filter (blocks < NAFF)  +  mem_v transpose -
__global__ void __launch_bounds__(256, 2) k_affA_tr(const float* __restrict__ qk,
                                                    const float* __restrict__ mv) {
    extern __shared__ char sm[];
    const int tid = threadIdx.x;

    if (blockIdx.x >= NAFF) {
        // ---- transpose block: mem_v [1536][M] -> fp16 g_vth [M][1536] ----
        int t = blockIdx.x - NAFF;
        const int m0 = (t % TRX) * 64, c0 = (t / TRX) * 64;
        float (*tile)[65] = (float (*)[65])sm;
        const int tx = tid & 15, ty = tid >> 4;

        float4 val[4];
        #pragma unroll
        for (int s = 0; s < 4; s++) {
            int c = c0 + s * 16 + ty;
            int m = m0 + tx * 4;
            val[s] = make_float4(0.f, 0.f, 0.f, 0.f);
            if (m < MD) val[s] = *(const float4*)(mv + (size_t)c * MD + m);
        }
        #pragma unroll
        for (int s = 0; s < 4; s++) {
            tile[s * 16 + ty][tx * 4 + 0] = val[s].x;
            tile[s * 16 + ty][tx * 4 + 1] = val[s].y;
            tile[s * 16 + ty][tx * 4 + 2] = val[s].z;
            tile[s * 16 + ty][tx * 4 + 3] = val[s].w;
        }
        __syncthreads();

        const int cl = (tid & 31) * 2;
        #pragma unroll
        for (int p = 0; p < 8; p++) {
            int r = p * 8 + (tid >> 5);
            int m = m0 + r;
            if (m < MD) {
                __half2 h = __floats2half2_rn(tile[cl][r], tile[cl + 1][r]);
                *(__half2*)(&g_vth[(size_t)m * CHD + c0 + cl]) = h;
            }
        }
        return;
    }

    // ---- affA block: filter GEMM -> per-(q,chunk) max ----
    __nv_bfloat16* qkb = (__nv_bfloat16*)(sm + SB_QKB);
    unsigned* red = (unsigned*)(sm + SB_RED);
    const uint32_t sbase = (uint32_t)__cvta_generic_to_shared(sm);

    const int lane = tid & 31, wid = tid >> 5;
    const int qw = wid >> 1, mw = wid & 1;
    const int r8 = lane >> 2, t4 = lane & 3;
    const int q0 = (blockIdx.x % NQB) * QT;
    const int chunk = blockIdx.x / NQB;
    const int mc0 = chunk * CHUNKP;

    STAGE_QKB();
    if (tid < QT) red[tid] = 0u;

    #pragma unroll
    for (int s = 0; s < NSTAGE - 1; s++) {
        STAGE_B_ASYNC(s, mc0 + s * MTILE);
        CP_COMMIT();
    }
    __syncthreads();

    uint32_t afr[2][4][4];
    LOAD_AFR();

    float rmax[4] = {-3.0e38f, -3.0e38f, -3.0e38f, -3.0e38f};

    for (int it = 0; it < ITERS1; it++) {
        const int s = it & (NSTAGE - 1);
        CP_WAIT2();
        __syncthreads();

        float acc[2][4][4];
        #pragma unroll
        for (int i = 0; i < 2; i++)
            #pragma unroll
            for (int j = 0; j < 4; j++)
                #pragma unroll
                for (int e = 0; e < 4; e++) acc[i][j][e] = 0.f;

        DO_MMA(s);

        if (it + NSTAGE - 1 < ITERS1) {
            STAGE_B_ASYNC((it + NSTAGE - 1) & (NSTAGE - 1), mc0 + (it + NSTAGE - 1) * MTILE);
        }
        CP_COMMIT();

        const float* nq = (const float*)(sm + SB_NASQ + s * 256);
        #pragma unroll
        for (int Mt = 0; Mt < 2; Mt++) {
            #pragma unroll
            for (int Nt = 0; Nt < 4; Nt++) {
                int ml = mw * 32 + Nt * 8 + 2 * t4;
                float2 nn = *(const float2*)&nq[ml];
                float a0 = fmaxf(0.25f * acc[Mt][Nt][0] + nn.x, 0.25f * acc[Mt][Nt][1] + nn.y);
                float a1 = fmaxf(0.25f * acc[Mt][Nt][2] + nn.x, 0.25f * acc[Mt][Nt][3] + nn.y);
                rmax[2 * Mt + 0] = fmaxf(rmax[2 * Mt + 0], a0);
                rmax[2 * Mt + 1] = fmaxf(rmax[2 * Mt + 1], a1);
            }
        }
    }

    #pragma unroll
    for (int i = 0; i < 4; i++) {
        #pragma unroll
        for (int s2 = 1; s2 <= 2; s2 <<= 1) {
            float o = __shfl_xor_sync(0xffffffffu, rmax[i], s2);
            rmax[i] = fmaxf(rmax[i], o);
        }
    }
    if (t4 == 0) {
        #pragma unroll
        for (int i = 0; i < 4; i++) {
            int row = qw * 32 + (i >> 1) * 16 + r8 + (i & 1) * 8;
            atomicMax(&red[row], encf(rmax[i]));
        }
    }
    __syncthreads();
    if (tid < QT) g_chunkmax[(q0 + tid) * NCHUNK + chunk] = red[tid];
}

// ---------------- K2: filter GEMM pass B -> collect hits >= threshold --------
__global__ void __launch_bounds__(256, 2) k_affB(const float* __restrict__ qk) {
    extern __shared__ char sm[];
    __nv_bfloat16* qkb = (__nv_bfloat16*)(sm + SB_QKB);
    const uint32_t sbase = (uint32_t)__cvta_generic_to_shared(sm);

    const int tid = threadIdx.x, lane = tid & 31, wid = tid >> 5;
    const int qw = wid >> 1, mw = wid & 1;
    const int r8 = lane >> 2, t4 = lane & 3;
    const int q0 = blockIdx.x * QT;
    const int chunk = blockIdx.y;
    const int mc0 = chunk * CHUNKP;

    STAGE_QKB();

    #pragma unroll
    for (int s = 0; s < NSTAGE - 1; s++) {
        STAGE_B_ASYNC(s, mc0 + s * MTILE);
        CP_COMMIT();
    }

    // inline per-q thresholds (3rd-smallest encoded = 20th-largest chunk max)
    float T[4];
    int qg[4];
    #pragma unroll
    for (int i = 0; i < 4; i++) {
        int row = qw * 32 + (i >> 1) * 16 + r8 + (i & 1) * 8;
        qg[i] = q0 + row;
        if (qg[i] < QD) {
            unsigned s1 = 0xFFFFFFFFu, s2 = 0xFFFFFFFFu, s3 = 0xFFFFFFFFu;
            const unsigned* cm = &g_chunkmax[qg[i] * NCHUNK];
            #pragma unroll
            for (int c = 0; c < NCHUNK; c++) {
                unsigned u = cm[c];
                if (u < s1)      { s3 = s2; s2 = s1; s1 = u; }
                else if (u < s2) { s3 = s2; s2 = u; }
                else if (u < s3) { s3 = u; }
            }
            T[i] = decf(s3) - 0.0625f;
        } else {
            T[i] = 3.4e38f;
        }
    }
    __syncthreads();

    uint32_t afr[2][4][4];
    LOAD_AFR();

    for (int it = 0; it < ITERS1; it++) {
        const int s = it & (NSTAGE - 1);
        const int m_base = mc0 + it * MTILE;
        CP_WAIT2();
        __syncthreads();

        float acc[2][4][4];
        #pragma unroll
        for (int i = 0; i < 2; i++)
            #pragma unroll
            for (int j = 0; j < 4; j++)
                #pragma unroll
                for (int e = 0; e < 4; e++) acc[i][j][e] = 0.f;

        DO_MMA(s);

        if (it + NSTAGE - 1 < ITERS1) {
            STAGE_B_ASYNC((it + NSTAGE - 1) & (NSTAGE - 1), mc0 + (it + NSTAGE - 1) * MTILE);
        }
        CP_COMMIT();

        const float* nq = (const float*)(sm + SB_NASQ + s * 256);
        #pragma unroll
        for (int Mt = 0; Mt < 2; Mt++) {
            #pragma unroll
            for (int Nt = 0; Nt < 4; Nt++) {
                int ml = mw * 32 + Nt * 8 + 2 * t4;
                float2 nn = *(const float2*)&nq[ml];
                float v00 = 0.25f * acc[Mt][Nt][0] + nn.x;
                float v01 = 0.25f * acc[Mt][Nt][1] + nn.y;
                float v10 = 0.25f * acc[Mt][Nt][2] + nn.x;
                float v11 = 0.25f * acc[Mt][Nt][3] + nn.y;
                int i0 = 2 * Mt, i1 = 2 * Mt + 1;
                if (v00 >= T[i0]) {
                    int p = atomicAdd(&g_hcnt[qg[i0]], 1);
                    if (p < HCAP) g_hits[(size_t)qg[i0] * HCAP + p] = m_base + ml;
                }
                if (v01 >= T[i0]) {
                    int p = atomicAdd(&g_hcnt[qg[i0]], 1);
                    if (p < HCAP) g_hits[(size_t)qg[i0] * HCAP + p] = m_base + ml + 1;
                }
                if (v10 >= T[i1]) {
                    int p = atomicAdd(&g_hcnt[qg[i1]], 1);
                    if (p < HCAP) g_hits[(size_t)qg[i1] * HCAP + p] = m_base + ml;
                }
                if (v11 >= T[i1]) {
                    int p = atomicAdd(&g_hcnt[qg[i1]], 1);
                    if (p < HCAP) g_hits[(size_t)qg[i1] * HCAP + p] = m_base + ml + 1;
                }
            }
        }
    }
}

// ---------------- K3: exact fp32 eval of hits + top-20 + softmax -------------
__global__ void k_rescue(const float* __restrict__ qk) {
    __shared__ int   pool[8][HCAP];
    __shared__ float pval[8][HCAP];
    __shared__ float qcol[8][CKD];

    int w = threadIdx.x >> 5, lane = threadIdx.x & 31;
    int q = blockIdx.x * 8 + w;
    if (q >= QD) return;

    qcol[w][lane] = qk[lane * QD + q];
    qcol[w][lane + 32] = qk[(lane + 32) * QD + q];
    int cnt = g_hcnt[q];
    if (cnt > HCAP) cnt = HCAP;
    const int* hp = g_hits + (size_t)q * HCAP;
    for (int i = lane; i < cnt; i += 32) pool[w][i] = hp[i];
    __syncwarp();

    for (int i = lane; i < cnt; i += 32) {
        int m = pool[w][i];
        const float4* kr = (const float4*)(g_mktf + (size_t)m * CKD);
        float dot = 0.f;
        #pragma unroll
        for (int c4 = 0; c4 < 16; c4++) {
            float4 kv = kr[c4];
            dot += kv.x * qcol[w][c4 * 4 + 0] + kv.y * qcol[w][c4 * 4 + 1]
                 + kv.z * qcol[w][c4 * 4 + 2] + kv.w * qcol[w][c4 * 4 + 3];
        }
        pval[w][i] = 0.25f * dot + g_nasq[m];
    }
    __syncwarp();

    uint64_t bestk = 0;
    for (int i = lane; i < cnt; i += 32) {
        uint64_t k = ((uint64_t)encf(pval[w][i]) << 32) | (uint32_t)(0xFFFFFFFFu - (uint32_t)pool[w][i]);
        if (k > bestk) bestk = k;
    }

    float vmax = 0.f, sum = 0.f;
    float myv = 0.f;
    int   myi = 0;
    for (int r = 0; r < TOPK; r++) {
        uint64_t k = bestk;
        #pragma unroll
        for (int s = 16; s > 0; s >>= 1) {
            uint64_t o = __shfl_xor_sync(0xffffffffu, k, s);
            if (o > k) k = o;
        }
        float kv = decf((unsigned)(k >> 32));
        if (r == 0) vmax = kv;
        sum += expf(kv - vmax);
        if (lane == r) { myv = kv; myi = (int)(0xFFFFFFFFu - (uint32_t)k); }
        if (k == bestk && k != 0) {
            uint64_t nb = 0;
            for (int i = lane; i < cnt; i += 32) {
                uint64_t kk = ((uint64_t)encf(pval[w][i]) << 32) | (uint32_t)(0xFFFFFFFFu - (uint32_t)pool[w][i]);
                if (kk == k) pval[w][i] = -3.4e38f;
                else if (kk > nb && kk < k) nb = kk;
            }
            bestk = nb;
        }
    }
    if (lane < TOPK) {
        g_wval[q * TOPK + lane] = expf(myv - vmax) / sum;
        g_widx[q * TOPK + lane] = myi;
    }
}

// ---------------- K4: sparse readout (fp16 v, half2 loads) -------------------
__global__ void k_readout(float* __restrict__ out) {
    __shared__ float sw[QT3 * TOPK];
    __shared__ int   si[QT3 * TOPK];
    int q0 = blockIdx.x * QT3;
    int ch2 = blockIdx.y * 256 + threadIdx.x;   // half2 index
    for (int t = threadIdx.x; t < QT3 * TOPK; t += 256) {
        int q = q0 + t / TOPK;
        if (q < QD) {
            sw[t] = g_wval[q * TOPK + (t % TOPK)];
            si[t] = g_widx[q * TOPK + (t % TOPK)];
        } else { sw[t] = 0.f; si[t] = 0; }
    }
    __syncthreads();

    const __half2* vt2 = (const __half2*)g_vth;
    float2 acc[QT3];
    #pragma unroll
    for (int j = 0; j < QT3; j++) acc[j] = make_float2(0.f, 0.f);

    #pragma unroll
    for (int k = 0; k < TOPK; k++) {
        #pragma unroll
        for (int j = 0; j < QT3; j++) {
            float w = sw[j * TOPK + k];
            int   m = si[j * TOPK + k];
            float2 f = __half22float2(vt2[(size_t)m * (CHD / 2) + ch2]);
            acc[j].x += w * f.x;
            acc[j].y += w * f.y;
        }
    }

    int ch0 = ch2 * 2;
    if (q0 + QT3 <= QD) {
        float4* o0 = (float4*)(out + (size_t)ch0 * QD + q0);
        float4* o1 = (float4*)(out + (size_t)(ch0 + 1) * QD + q0);
        #pragma unroll
        for (int jj = 0; jj < QT3 / 4; jj++) {
            o0[jj] = make_float4(acc[jj*4].x, acc[jj*4+1].x, acc[jj*4+2].x, acc[jj*4+3].x);
            o1[jj] = make_float4(acc[jj*4].y, acc[jj*4+1].y, acc[jj*4+2].y, acc[jj*4+3].y);
        }
    } else {
        #pragma unroll
        for (int j = 0; j < QT3; j++) {
            int q = q0 + j;
            if (q < QD) {
                out[(size_t)ch0 * QD + q] = acc[j].x;
                out[(size_t)(ch0 + 1) * QD + q] = acc[j].y;
            }
        }
    }
}

// ---------------- launch ----------------
extern "C" void kernel_launch(void* const* d_in, const int* in_sizes, int n_in,
                              void* d_out, int out_size) {
    const float* qk = (const float*)d_in[0];   // [64][1620]
    const float* mk = (const float*)d_in[1];   // [64][32400]
    const float* mv = (const float*)d_in[2];   // [1536][32400]
    float* out = (float*)d_out;                // [1536][1620]
    (void)in_sizes; (void)n_in; (void)out_size;

    k_prep<<<MPAD / 32, 256>>>(mk);                                          // 1

    cudaFuncSetAttribute(k_affA_tr, cudaFuncAttributeMaxDynamicSharedMemorySize, SB_TOTAL);
    cudaFuncSetAttribute(k_affB, cudaFuncAttributeMaxDynamicSharedMemorySize, SB_TOTAL);
    k_affA_tr<<<NAFF + NTR, 256, SB_TOTAL>>>(qk, mv);                        // 2 (fused)

    k_affB<<<dim3(NQB, NCHUNK), 256, SB_TOTAL>>>(qk);                        // 3
    k_rescue<<<(QD + 7) / 8, 256>>>(qk);                                     // 4 (ncu slot)
    k_readout<<<dim3((QD + QT3 - 1) / QT3, CHD / 512), 256>>>(out);          // 5
}

// round 13
// speedup vs baseline: 1.0943x; 1.0943x over previous
#include <cuda_runtime.h>
#include <cuda_bf16.h>
#include <cuda_fp16.h>
#include <math.h>
#include <stdint.h>

// ---------------- problem constants ----------------
#define CKD 64
#define QD 1620          // H*W
#define MD 32400
#define TOPK 20
#define CHD 1536         // OD*CVD

// ---------------- filter tiling ----------------
#define QT 128           // q per block
#define MTILE 64         // m per iteration
#define NQB 13           // 13*128 = 1664 >= 1620
#define NCHUNK 22
#define CHUNKP 1536      // m per chunk
#define ITERS1 24        // CHUNKP / MTILE
#define MPAD (NCHUNK * CHUNKP)   // 33792
#define HCAP 512         // per-q hit capacity
#define NSTAGE 4
#define QT3 16

// ---------------- device scratch ----------------
__device__ __align__(16) float g_nasq[MPAD];
__device__ __align__(16) __nv_bfloat16 g_mkt[(size_t)MPAD * CKD];
__device__ __align__(16) float g_mktf[(size_t)MD * CKD];
__device__ __align__(16) __half g_vth[(size_t)MD * CHD];
__device__ unsigned g_chunkmax[NQB * QT * NCHUNK];
__device__ int   g_hcnt[QD];
__device__ int   g_hits[(size_t)QD * HCAP];
__device__ float g_wval[QD * TOPK];
__device__ int   g_widx[QD * TOPK];

// order-preserving float<->uint map (unsigned domain)
__device__ __forceinline__ unsigned encf(float v) {
    unsigned b = __float_as_uint(v);
    return (b & 0x80000000u) ? ~b : (b | 0x80000000u);
}
__device__ __forceinline__ float decf(unsigned u) {
    unsigned b = (u & 0x80000000u) ? (u & 0x7FFFFFFFu) : ~u;
    return __uint_as_float(b);
}

// ---------------- async copy helpers ----------------
#define CP_ASYNC16(dst, src) \
    asm volatile("cp.async.cg.shared.global [%0], [%1], 16;" :: "r"(dst), "l"(src))
#define CP_COMMIT() asm volatile("cp.async.commit_group;")
#define CP_WAIT2()  asm volatile("cp.async.wait_group 2;" ::: "memory")

// ---------------- mma helper ----------------
__device__ __forceinline__ void mma_bf16(float* c, const uint32_t* a,
                                         uint32_t b0, uint32_t b1) {
    asm volatile(
        "mma.sync.aligned.m16n8k16.row.col.f32.bf16.bf16.f32 "
        "{%0,%1,%2,%3}, {%4,%5,%6,%7}, {%8,%9}, {%0,%1,%2,%3};"
        : "+f"(c[0]), "+f"(c[1]), "+f"(c[2]), "+f"(c[3])
        : "r"(a[0]), "r"(a[1]), "r"(a[2]), "r"(a[3]), "r"(b0), "r"(b1));
}

// ---------------- K0: prep — mk transpose (bf16+fp32) + nasq + hcnt zero -----
__global__ void __launch_bounds__(256) k_prep(const float* __restrict__ mk) {
    __shared__ float tile[CKD][33];
    const int m0 = blockIdx.x * 32;
    const int tid = threadIdx.x;

    int gz = blockIdx.x * 256 + tid;
    if (gz < QD) g_hcnt[gz] = 0;

    {
        int ml = tid & 31;
        int m = m0 + ml;
        #pragma unroll
        for (int i = 0; i < 8; i++) {
            int c = (tid >> 5) + i * 8;
            tile[c][ml] = (m < MD) ? mk[(size_t)c * MD + m] : 0.f;
        }
    }
    __syncthreads();

    #pragma unroll
    for (int i = 0; i < 8; i++) {
        int idx = tid + i * 256;
        int ml = idx >> 6, c = idx & 63;
        float v = tile[c][ml];
        int m = m0 + ml;
        g_mkt[(size_t)m * CKD + c] = __float2bfloat16(v);
        if (m < MD) g_mktf[(size_t)m * CKD + c] = v;
    }

    if (tid < 32) {
        int m = m0 + tid;
        float s = 0.f;
        #pragma unroll
        for (int c = 0; c < CKD; c++) {
            float v = tile[c][tid];
            s += v * v;
        }
        g_nasq[m] = (m < MD) ? -(s * 0.125f) : -1.0e37f;
    }
}

// ---------------- KT: mem_v transpose [1536][M] -> fp16 [M][1536] ------------
// 32x32 conflict-free tile (proven layout)
__global__ void k_transpose(const float* __restrict__ v) {
    __shared__ float tile[32][33];
    int m0 = blockIdx.x * 32, c0 = blockIdx.y * 32;
    int tx = threadIdx.x, ty = threadIdx.y;
    #pragma unroll
    for (int i = ty; i < 32; i += 8) {
        int m = m0 + tx;
        tile[i][tx] = (m < MD) ? v[(size_t)(c0 + i) * MD + m] : 0.f;
    }
    __syncthreads();
    #pragma unroll
    for (int i = ty; i < 32; i += 8) {
        int m = m0 + i;
        if (m < MD) g_vth[(size_t)m * CHD + c0 + tx] = __float2half(tile[tx][i]);
    }
}

// ---------------- filter GEMM common smem layout (bytes) ----------------
#define SB_QKB   0                       // bf16 qk [128][68] = 17408
#define SB_B     17408                   // NSTAGE x (64 rows x 144B) = 36864
#define SB_NASQ  54272                   // NSTAGE x 256B = 1024
#define SB_RED   55296                   // 128 unsigned = 512
#define SB_TOTAL 55808

#define STAGE_B_ASYNC(s, mb) do { \
    const char* _gs = (const char*)g_mkt + (size_t)(mb) * (CKD * 2); \
    uint32_t _bb = sbase + SB_B + (s) * 9216; \
    _Pragma("unroll") \
    for (int _i = 0; _i < 2; _i++) { \
        int _idx = tid + _i * 256; \
        int _m = _idx >> 3, _c16 = _idx & 7; \
        CP_ASYNC16(_bb + _m * 144 + _c16 * 16, _gs + _m * 128 + _c16 * 16); \
    } \
    if (tid < 16) \
        CP_ASYNC16(sbase + SB_NASQ + (s) * 256 + tid * 16, \
                   (const char*)g_nasq + (size_t)(mb) * 4 + tid * 16); \
} while (0)

#define STAGE_QKB() do { \
    for (int t = tid; t < CKD * QT; t += 256) { \
        int c = t >> 7, j = t & 127; \
        int q = q0 + j; \
        float v = (q < QD) ? qk[c * QD + q] : 0.f; \
        qkb[j * 68 + c] = __float2bfloat16(v); \
    } \
} while (0)

#define LOAD_AFR() do { \
    _Pragma("unroll") \
    for (int Mt = 0; Mt < 2; Mt++) { \
        _Pragma("unroll") \
        for (int ks = 0; ks < 4; ks++) { \
            int qr = qw * 32 + Mt * 16 + r8; \
            int cc = ks * 16 + 2 * t4; \
            afr[Mt][ks][0] = *(const uint32_t*)&qkb[qr * 68 + cc]; \
            afr[Mt][ks][1] = *(const uint32_t*)&qkb[(qr + 8) * 68 + cc]; \
            afr[Mt][ks][2] = *(const uint32_t*)&qkb[qr * 68 + cc + 8]; \
            afr[Mt][ks][3] = *(const uint32_t*)&qkb[(qr + 8) * 68 + cc + 8]; \
        } \
    } \
} while (0)

#define DO_MMA(s) do { \
    const uint32_t* Bb = (const uint32_t*)(sm + SB_B + (s) * 9216); \
    _Pragma("unroll") \
    for (int ks = 0; ks < 4; ks++) { \
        _Pragma("unroll") \
        for (int Nt = 0; Nt < 4; Nt++) { \
            int nl = mw * 32 + Nt * 8 + r8; \
            uint32_t b0 = Bb[nl * 36 + ks * 8 + t4]; \
            uint32_t b1 = Bb[nl * 36 + ks * 8 + t4 + 4]; \
            mma_bf16(acc[0][Nt], afr[0][ks], b0, b1); \
            mma_bf16(acc[1][Nt], afr[1][ks], b0, b1); \
        } \
    } \
} while (0)

// ---------------- K1: filter GEMM pass A -> per-(q,chunk) max ----------------
__global__ void __launch_bounds__(256, 2) k_affA(const float* __restrict__ qk) {
    extern __shared__ char sm[];
    __nv_bfloat16* qkb = (__nv_bfloat16*)(sm + SB_QKB);
    unsigned* red = (unsigned*)(sm + SB_RED);
    const uint32_t sbase = (uint32_t)__cvta_generic_to_shared(sm);

    const int tid = threadIdx.x, lane = tid & 31, wid = tid >> 5;
    const int qw = wid >> 1, mw = wid & 1;
    const int r8 = lane >> 2, t4 = lane & 3;
    const int q0 = blockIdx.x * QT;
    const int chunk = blockIdx.y;
    const int mc0 = chunk * CHUNKP;

    STAGE_QKB();
    if (tid < QT) red[tid] = 0u;

    #pragma unroll
    for (int s = 0; s < NSTAGE - 1; s++) {
        STAGE_B_ASYNC(s, mc0 + s * MTILE);
        CP_COMMIT();
    }
    __syncthreads();

    uint32_t afr[2][4][4];
    LOAD_AFR();

    float rmax[4] = {-3.0e38f, -3.0e38f, -3.0e38f, -3.0e38f};

    for (int it = 0; it < ITERS1; it++) {
        const int s = it & (NSTAGE - 1);
        CP_WAIT2();
        __syncthreads();

        float acc[2][4][4];
        #pragma unroll
        for (int i = 0; i < 2; i++)
            #pragma unroll
            for (int j = 0; j < 4; j++)
                #pragma unroll
                for (int e = 0; e < 4; e++) acc[i][j][e] = 0.f;

        DO_MMA(s);

        if (it + NSTAGE - 1 < ITERS1) {
            STAGE_B_ASYNC((it + NSTAGE - 1) & (NSTAGE - 1), mc0 + (it + NSTAGE - 1) * MTILE);
        }
        CP_COMMIT();

        const float* nq = (const float*)(sm + SB_NASQ + s * 256);
        #pragma unroll
        for (int Mt = 0; Mt < 2; Mt++) {
            #pragma unroll
            for (int Nt = 0; Nt < 4; Nt++) {
                int ml = mw * 32 + Nt * 8 + 2 * t4;
                float2 nn = *(const float2*)&nq[ml];
                float a0 = fmaxf(0.25f * acc[Mt][Nt][0] + nn.x, 0.25f * acc[Mt][Nt][1] + nn.y);
                float a1 = fmaxf(0.25f * acc[Mt][Nt][2] + nn.x, 0.25f * acc[Mt][Nt][3] + nn.y);
                rmax[2 * Mt + 0] = fmaxf(rmax[2 * Mt + 0], a0);
                rmax[2 * Mt + 1] = fmaxf(rmax[2 * Mt + 1], a1);
            }
        }
    }

    #pragma unroll
    for (int i = 0; i < 4; i++) {
        #pragma unroll
        for (int s2 = 1; s2 <= 2; s2 <<= 1) {
            float o = __shfl_xor_sync(0xffffffffu, rmax[i], s2);
            rmax[i] = fmaxf(rmax[i], o);
        }
    }
    if (t4 == 0) {
        #pragma unroll
        for (int i = 0; i < 4; i++) {
            int row = qw * 32 + (i >> 1) * 16 + r8 + (i & 1) * 8;
            atomicMax(&red[row], encf(rmax[i]));
        }
    }
    __syncthreads();
    if (tid < QT) g_chunkmax[(q0 + tid) * NCHUNK + chunk] = red[tid];
}

// ---------------- K2: filter GEMM pass B -> collect hits >= threshold --------
__global__ void __launch_bounds__(256, 2) k_affB(const float* __restrict__ qk) {
    extern __shared__ char sm[];
    __nv_bfloat16* qkb = (__nv_bfloat16*)(sm + SB_QKB);
    const uint32_t sbase = (uint32_t)__cvta_generic_to_shared(sm);

    const int tid = threadIdx.x, lane = tid & 31, wid = tid >> 5;
    const int qw = wid >> 1, mw = wid & 1;
    const int r8 = lane >> 2, t4 = lane & 3;
    const int q0 = blockIdx.x * QT;
    const int chunk = blockIdx.y;
    const int mc0 = chunk * CHUNKP;

    STAGE_QKB();

    #pragma unroll
    for (int s = 0; s < NSTAGE - 1; s++) {
        STAGE_B_ASYNC(s, mc0 + s * MTILE);
        CP_COMMIT();
    }

    // inline per-q thresholds (3rd-smallest encoded = 20th-largest chunk max)
    float T[4];
    int qg[4];
    #pragma unroll
    for (int i = 0; i < 4; i++) {
        int row = qw * 32 + (i >> 1) * 16 + r8 + (i & 1) * 8;
        qg[i] = q0 + row;
        if (qg[i] < QD) {
            unsigned s1 = 0xFFFFFFFFu, s2 = 0xFFFFFFFFu, s3 = 0xFFFFFFFFu;
            const unsigned* cm = &g_chunkmax[qg[i] * NCHUNK];
            #pragma unroll
            for (int c = 0; c < NCHUNK; c++) {
                unsigned u = cm[c];
                if (u < s1)      { s3 = s2; s2 = s1; s1 = u; }
                else if (u < s2) { s3 = s2; s2 = u; }
                else if (u < s3) { s3 = u; }
            }
            T[i] = decf(s3) - 0.0625f;
        } else {
            T[i] = 3.4e38f;
        }
    }
    __syncthreads();

    uint32_t afr[2][4][4];
    LOAD_AFR();

    for (int it = 0; it < ITERS1; it++) {
        const int s = it & (NSTAGE - 1);
        const int m_base = mc0 + it * MTILE;
        CP_WAIT2();
        __syncthreads();

        float acc[2][4][4];
        #pragma unroll
        for (int i = 0; i < 2; i++)
            #pragma unroll
            for (int j = 0; j < 4; j++)
                #pragma unroll
                for (int e = 0; e < 4; e++) acc[i][j][e] = 0.f;

        DO_MMA(s);

        if (it + NSTAGE - 1 < ITERS1) {
            STAGE_B_ASYNC((it + NSTAGE - 1) & (NSTAGE - 1), mc0 + (it + NSTAGE - 1) * MTILE);
        }
        CP_COMMIT();

        const float* nq = (const float*)(sm + SB_NASQ + s * 256);
        #pragma unroll
        for (int Mt = 0; Mt < 2; Mt++) {
            #pragma unroll
            for (int Nt = 0; Nt < 4; Nt++) {
                int ml = mw * 32 + Nt * 8 + 2 * t4;
                float2 nn = *(const float2*)&nq[ml];
                float v00 = 0.25f * acc[Mt][Nt][0] + nn.x;
                float v01 = 0.25f * acc[Mt][Nt][1] + nn.y;
                float v10 = 0.25f * acc[Mt][Nt][2] + nn.x;
                float v11 = 0.25f * acc[Mt][Nt][3] + nn.y;
                int i0 = 2 * Mt, i1 = 2 * Mt + 1;
                if (v00 >= T[i0]) {
                    int p = atomicAdd(&g_hcnt[qg[i0]], 1);
                    if (p < HCAP) g_hits[(size_t)qg[i0] * HCAP + p] = m_base + ml;
                }
                if (v01 >= T[i0]) {
                    int p = atomicAdd(&g_hcnt[qg[i0]], 1);
                    if (p < HCAP) g_hits[(size_t)qg[i0] * HCAP + p] = m_base + ml + 1;
                }
                if (v10 >= T[i1]) {
                    int p = atomicAdd(&g_hcnt[qg[i1]], 1);
                    if (p < HCAP) g_hits[(size_t)qg[i1] * HCAP + p] = m_base + ml;
                }
                if (v11 >= T[i1]) {
                    int p = atomicAdd(&g_hcnt[qg[i1]], 1);
                    if (p < HCAP) g_hits[(size_t)qg[i1] * HCAP + p] = m_base + ml + 1;
                }
            }
        }
    }
}

// ---------------- K3: exact fp32 eval of hits + rank-count top-20 + softmax --
__global__ void k_rescue(const float* __restrict__ qk) {
    __shared__ int   pool[8][HCAP];
    __shared__ float pval[8][HCAP];
    __shared__ float qcol[8][CKD];
    __shared__ float sval[8][TOPK];
    __shared__ int   sidx[8][TOPK];

    int w = threadIdx.x >> 5, lane = threadIdx.x & 31;
    int q = blockIdx.x * 8 + w;
    if (q >= QD) return;

    qcol[w][lane] = qk[lane * QD + q];
    qcol[w][lane + 32] = qk[(lane + 32) * QD + q];
    int cnt = g_hcnt[q];
    if (cnt > HCAP) cnt = HCAP;
    const int* hp = g_hits + (size_t)q * HCAP;
    for (int i = lane; i < cnt; i += 32) pool[w][i] = hp[i];
    __syncwarp();

    // exact fp32 affinity for each hit
    for (int i = lane; i < cnt; i += 32) {
        int m = pool[w][i];
        const float4* kr = (const float4*)(g_mktf + (size_t)m * CKD);
        float dot = 0.f;
        #pragma unroll
        for (int c4 = 0; c4 < 16; c4++) {
            float4 kv = kr[c4];
            dot += kv.x * qcol[w][c4 * 4 + 0] + kv.y * qcol[w][c4 * 4 + 1]
                 + kv.z * qcol[w][c4 * 4 + 2] + kv.w * qcol[w][c4 * 4 + 3];
        }
        pval[w][i] = 0.25f * dot + g_nasq[m];
    }
    __syncwarp();

    // rank-count selection (strict total order: val desc, idx asc) — ranks unique
    for (int i = lane; i < cnt; i += 32) {
        float vi = pval[w][i];
        int   ii = pool[w][i];
        int rank = 0;
        for (int j = 0; j < cnt; j++) {
            float vj = pval[w][j];
            int   ij = pool[w][j];
            rank += (vj > vi || (vj == vi && ij < ii)) ? 1 : 0;
        }
        if (rank < TOPK) { sval[w][rank] = vi; sidx[w][rank] = ii; }
    }
    __syncwarp();

    // softmax over the 20 selected (cnt >= 20 guaranteed by threshold construction)
    float v = (lane < TOPK) ? sval[w][lane] : -3.4e38f;
    float mx = v;
    #pragma unroll
    for (int s = 16; s > 0; s >>= 1) {
        float o = __shfl_xor_sync(0xffffffffu, mx, s);
        if (o > mx) mx = o;
    }
    float e = (lane < TOPK) ? expf(v - mx) : 0.f;
    float sum = e;
    #pragma unroll
    for (int s = 16; s > 0; s >>= 1) sum += __shfl_xor_sync(0xffffffffu, sum, s);
    if (lane < TOPK) {
        g_wval[q * TOPK + lane] = e / sum;
        g_widx[q * TOPK + lane] = sidx[w][lane];
    }
}

// ---------------- K4: sparse readout (fp16 v, half2 loads) -------------------
__global__ void k_readout(float* __restrict__ out) {
    __shared__ float sw[QT3 * TOPK];
    __shared__ int   si[QT3 * TOPK];
    int q0 = blockIdx.x * QT3;
    int ch2 = blockIdx.y * 256 + threadIdx.x;   // half2 index
    for (int t = threadIdx.x; t < QT3 * TOPK; t += 256) {
        int q = q0 + t / TOPK;
        if (q < QD) {
            sw[t] = g_wval[q * TOPK + (t % TOPK)];
            si[t] = g_widx[q * TOPK + (t % TOPK)];
        } else { sw[t] = 0.f; si[t] = 0; }
    }
    __syncthreads();

    const __half2* vt2 = (const __half2*)g_vth;
    float2 acc[QT3];
    #pragma unroll
    for (int j = 0; j < QT3; j++) acc[j] = make_float2(0.f, 0.f);

    #pragma unroll
    for (int k = 0; k < TOPK; k++) {
        #pragma unroll
        for (int j = 0; j < QT3; j++) {
            float w = sw[j * TOPK + k];
            int   m = si[j * TOPK + k];
            float2 f = __half22float2(vt2[(size_t)m * (CHD / 2) + ch2]);
            acc[j].x += w * f.x;
            acc[j].y += w * f.y;
        }
    }

    int ch0 = ch2 * 2;
    if (q0 + QT3 <= QD) {
        float4* o0 = (float4*)(out + (size_t)ch0 * QD + q0);
        float4* o1 = (float4*)(out + (size_t)(ch0 + 1) * QD + q0);
        #pragma unroll
        for (int jj = 0; jj < QT3 / 4; jj++) {
            o0[jj] = make_float4(acc[jj*4].x, acc[jj*4+1].x, acc[jj*4+2].x, acc[jj*4+3].x);
            o1[jj] = make_float4(acc[jj*4].y, acc[jj*4+1].y, acc[jj*4+2].y, acc[jj*4+3].y);
        }
    } else {
        #pragma unroll
        for (int j = 0; j < QT3; j++) {
            int q = q0 + j;
            if (q < QD) {
                out[(size_t)ch0 * QD + q] = acc[j].x;
                out[(size_t)(ch0 + 1) * QD + q] = acc[j].y;
            }
        }
    }
}

// ---------------- launch ----------------
extern "C" void kernel_launch(void* const* d_in, const int* in_sizes, int n_in,
                              void* d_out, int out_size) {
    const float* qk = (const float*)d_in[0];   // [64][1620]
    const float* mk = (const float*)d_in[1];   // [64][32400]
    const float* mv = (const float*)d_in[2];   // [1536][32400]
    float* out = (float*)d_out;                // [1536][1620]
    (void)in_sizes; (void)n_in; (void)out_size;

    k_prep<<<MPAD / 32, 256>>>(mk);                                          // 1

    cudaFuncSetAttribute(k_affA, cudaFuncAttributeMaxDynamicSharedMemorySize, SB_TOTAL);
    cudaFuncSetAttribute(k_affB, cudaFuncAttributeMaxDynamicSharedMemorySize, SB_TOTAL);
    k_affA<<<dim3(NQB, NCHUNK), 256, SB_TOTAL>>>(qk);                        // 2

    k_transpose<<<dim3((MD + 31) / 32, CHD / 32), dim3(32, 8)>>>(mv);        // 3

    k_affB<<<dim3(NQB, NCHUNK), 256, SB_TOTAL>>>(qk);                        // 4 (ncu slot)
    k_rescue<<<(QD + 7) / 8, 256>>>(qk);                                     // 5
    k_readout<<<dim3((QD + QT3 - 1) / QT3, CHD / 512), 256>>>(out);          // 6
}

// round 14
// speedup vs baseline: 1.2255x; 1.1200x over previous
#include <cuda_runtime.h>
#include <cuda_bf16.h>
#include <cuda_fp16.h>
#include <math.h>
#include <stdint.h>

// ---------------- problem constants ----------------
#define CKD 64
#define QD 1620          // H*W
#define MD 32400
#define TOPK 20
#define CHD 1536         // OD*CVD

// ---------------- filter tiling ----------------
#define QT 128           // q per block
#define MTILE 64         // m per iteration
#define NQB 13           // 13*128 = 1664 >= 1620
#define NCHUNK 22
#define CHUNKP 1536      // m per chunk
#define ITERS1 24        // CHUNKP / MTILE
#define MPAD (NCHUNK * CHUNKP)   // 33792
#define HCAP 512         // per-q global hit capacity
#define CAP2 16          // per-(q,chunk) smem hit buffer capacity
#define NSTAGE 4
#define QT3 16

// ---------------- device scratch ----------------
__device__ __align__(16) float g_nasq[MPAD];
__device__ __align__(16) __nv_bfloat16 g_mkt[(size_t)MPAD * CKD];
__device__ __align__(16) float g_mktf[(size_t)MD * CKD];
__device__ __align__(16) __half g_vth[(size_t)MD * CHD];
__device__ unsigned g_chunkmax[NQB * QT * NCHUNK];
__device__ int   g_hcnt[QD];
__device__ int   g_hits[(size_t)QD * HCAP];
__device__ float g_wval[QD * TOPK];
__device__ int   g_widx[QD * TOPK];

// order-preserving float<->uint map (unsigned domain)
__device__ __forceinline__ unsigned encf(float v) {
    unsigned b = __float_as_uint(v);
    return (b & 0x80000000u) ? ~b : (b | 0x80000000u);
}
__device__ __forceinline__ float decf(unsigned u) {
    unsigned b = (u & 0x80000000u) ? (u & 0x7FFFFFFFu) : ~u;
    return __uint_as_float(b);
}

// ---------------- async copy helpers ----------------
#define CP_ASYNC16(dst, src) \
    asm volatile("cp.async.cg.shared.global [%0], [%1], 16;" :: "r"(dst), "l"(src))
#define CP_COMMIT() asm volatile("cp.async.commit_group;")
#define CP_WAIT2()  asm volatile("cp.async.wait_group 2;" ::: "memory")

// ---------------- mma helper ----------------
__device__ __forceinline__ void mma_bf16(float* c, const uint32_t* a,
                                         uint32_t b0, uint32_t b1) {
    asm volatile(
        "mma.sync.aligned.m16n8k16.row.col.f32.bf16.bf16.f32 "
        "{%0,%1,%2,%3}, {%4,%5,%6,%7}, {%8,%9}, {%0,%1,%2,%3};"
        : "+f"(c[0]), "+f"(c[1]), "+f"(c[2]), "+f"(c[3])
        : "r"(a[0]), "r"(a[1]), "r"(a[2]), "r"(a[3]), "r"(b0), "r"(b1));
}

// ---------------- K0: prep — mk transpose (bf16+fp32) + nasq + hcnt zero -----
__global__ void __launch_bounds__(256) k_prep(const float* __restrict__ mk) {
    __shared__ float tile[CKD][33];
    const int m0 = blockIdx.x * 32;
    const int tid = threadIdx.x;

    int gz = blockIdx.x * 256 + tid;
    if (gz < QD) g_hcnt[gz] = 0;

    {
        int ml = tid & 31;
        int m = m0 + ml;
        #pragma unroll
        for (int i = 0; i < 8; i++) {
            int c = (tid >> 5) + i * 8;
            tile[c][ml] = (m < MD) ? mk[(size_t)c * MD + m] : 0.f;
        }
    }
    __syncthreads();

    #pragma unroll
    for (int i = 0; i < 8; i++) {
        int idx = tid + i * 256;
        int ml = idx >> 6, c = idx & 63;
        float v = tile[c][ml];
        int m = m0 + ml;
        g_mkt[(size_t)m * CKD + c] = __float2bfloat16(v);
        if (m < MD) g_mktf[(size_t)m * CKD + c] = v;
    }

    if (tid < 32) {
        int m = m0 + tid;
        float s = 0.f;
        #pragma unroll
        for (int c = 0; c < CKD; c++) {
            float v = tile[c][tid];
            s += v * v;
        }
        g_nasq[m] = (m < MD) ? -(s * 0.125f) : -1.0e37f;
    }
}

// ---------------- KT: mem_v transpose [1536][M] -> fp16 [M][1536] ------------
__global__ void k_transpose(const float* __restrict__ v) {
    __shared__ float tile[32][33];
    int m0 = blockIdx.x * 32, c0 = blockIdx.y * 32;
    int tx = threadIdx.x, ty = threadIdx.y;
    #pragma unroll
    for (int i = ty; i < 32; i += 8) {
        int m = m0 + tx;
        tile[i][tx] = (m < MD) ? v[(size_t)(c0 + i) * MD + m] : 0.f;
    }
    __syncthreads();
    #pragma unroll
    for (int i = ty; i < 32; i += 8) {
        int m = m0 + i;
        if (m < MD) g_vth[(size_t)m * CHD + c0 + tx] = __float2half(tile[tx][i]);
    }
}

// ---------------- filter GEMM common smem layout (bytes) ----------------
#define SB_QKB   0                       // bf16 qk [128][68] = 17408
#define SB_B     17408                   // NSTAGE x (64 rows x 144B) = 36864
#define SB_NASQ  54272                   // NSTAGE x 256B = 1024
#define SB_RED   55296                   // 128 unsigned = 512 (affA)
#define SB_TOTAL 55808
// affB extras
#define SB_SCNT  55296                   // 128 int = 512
#define SB_SBUF  55808                   // 128 x CAP2 int = 8192
#define SB_TOTAL2 64000

#define STAGE_B_ASYNC(s, mb) do { \
    const char* _gs = (const char*)g_mkt + (size_t)(mb) * (CKD * 2); \
    uint32_t _bb = sbase + SB_B + (s) * 9216; \
    _Pragma("unroll") \
    for (int _i = 0; _i < 2; _i++) { \
        int _idx = tid + _i * 256; \
        int _m = _idx >> 3, _c16 = _idx & 7; \
        CP_ASYNC16(_bb + _m * 144 + _c16 * 16, _gs + _m * 128 + _c16 * 16); \
    } \
    if (tid < 16) \
        CP_ASYNC16(sbase + SB_NASQ + (s) * 256 + tid * 16, \
                   (const char*)g_nasq + (size_t)(mb) * 4 + tid * 16); \
} while (0)

#define STAGE_QKB() do { \
    for (int t = tid; t < CKD * QT; t += 256) { \
        int c = t >> 7, j = t & 127; \
        int q = q0 + j; \
        float v = (q < QD) ? qk[c * QD + q] : 0.f; \
        qkb[j * 68 + c] = __float2bfloat16(v); \
    } \
} while (0)

#define LOAD_AFR() do { \
    _Pragma("unroll") \
    for (int Mt = 0; Mt < 2; Mt++) { \
        _Pragma("unroll") \
        for (int ks = 0; ks < 4; ks++) { \
            int qr = qw * 32 + Mt * 16 + r8; \
            int cc = ks * 16 + 2 * t4; \
            afr[Mt][ks][0] = *(const uint32_t*)&qkb[qr * 68 + cc]; \
            afr[Mt][ks][1] = *(const uint32_t*)&qkb[(qr + 8) * 68 + cc]; \
            afr[Mt][ks][2] = *(const uint32_t*)&qkb[qr * 68 + cc + 8]; \
            afr[Mt][ks][3] = *(const uint32_t*)&qkb[(qr + 8) * 68 + cc + 8]; \
        } \
    } \
} while (0)

#define DO_MMA(s) do { \
    const uint32_t* Bb = (const uint32_t*)(sm + SB_B + (s) * 9216); \
    _Pragma("unroll") \
    for (int ks = 0; ks < 4; ks++) { \
        _Pragma("unroll") \
        for (int Nt = 0; Nt < 4; Nt++) { \
            int nl = mw * 32 + Nt * 8 + r8; \
            uint32_t b0 = Bb[nl * 36 + ks * 8 + t4]; \
            uint32_t b1 = Bb[nl * 36 + ks * 8 + t4 + 4]; \
            mma_bf16(acc[0][Nt], afr[0][ks], b0, b1); \
            mma_bf16(acc[1][Nt], afr[1][ks], b0, b1); \
        } \
    } \
} while (0)

// ---------------- K1: filter GEMM pass A -> per-(q,chunk) max ----------------
__global__ void __launch_bounds__(256, 2) k_affA(const float* __restrict__ qk) {
    extern __shared__ char sm[];
    __nv_bfloat16* qkb = (__nv_bfloat16*)(sm + SB_QKB);
    unsigned* red = (unsigned*)(sm + SB_RED);
    const uint32_t sbase = (uint32_t)__cvta_generic_to_shared(sm);

    const int tid = threadIdx.x, lane = tid & 31, wid = tid >> 5;
    const int qw = wid >> 1, mw = wid & 1;
    const int r8 = lane >> 2, t4 = lane & 3;
    const int q0 = blockIdx.x * QT;
    const int chunk = blockIdx.y;
    const int mc0 = chunk * CHUNKP;

    STAGE_QKB();
    if (tid < QT) red[tid] = 0u;

    #pragma unroll
    for (int s = 0; s < NSTAGE - 1; s++) {
        STAGE_B_ASYNC(s, mc0 + s * MTILE);
        CP_COMMIT();
    }
    __syncthreads();

    uint32_t afr[2][4][4];
    LOAD_AFR();

    float rmax[4] = {-3.0e38f, -3.0e38f, -3.0e38f, -3.0e38f};

    for (int it = 0; it < ITERS1; it++) {
        const int s = it & (NSTAGE - 1);
        CP_WAIT2();
        __syncthreads();

        float acc[2][4][4];
        #pragma unroll
        for (int i = 0; i < 2; i++)
            #pragma unroll
            for (int j = 0; j < 4; j++)
                #pragma unroll
                for (int e = 0; e < 4; e++) acc[i][j][e] = 0.f;

        DO_MMA(s);

        if (it + NSTAGE - 1 < ITERS1) {
            STAGE_B_ASYNC((it + NSTAGE - 1) & (NSTAGE - 1), mc0 + (it + NSTAGE - 1) * MTILE);
        }
        CP_COMMIT();

        const float* nq = (const float*)(sm + SB_NASQ + s * 256);
        #pragma unroll
        for (int Mt = 0; Mt < 2; Mt++) {
            #pragma unroll
            for (int Nt = 0; Nt < 4; Nt++) {
                int ml = mw * 32 + Nt * 8 + 2 * t4;
                float2 nn = *(const float2*)&nq[ml];
                float a0 = fmaxf(0.25f * acc[Mt][Nt][0] + nn.x, 0.25f * acc[Mt][Nt][1] + nn.y);
                float a1 = fmaxf(0.25f * acc[Mt][Nt][2] + nn.x, 0.25f * acc[Mt][Nt][3] + nn.y);
                rmax[2 * Mt + 0] = fmaxf(rmax[2 * Mt + 0], a0);
                rmax[2 * Mt + 1] = fmaxf(rmax[2 * Mt + 1], a1);
            }
        }
    }

    #pragma unroll
    for (int i = 0; i < 4; i++) {
        #pragma unroll
        for (int s2 = 1; s2 <= 2; s2 <<= 1) {
            float o = __shfl_xor_sync(0xffffffffu, rmax[i], s2);
            rmax[i] = fmaxf(rmax[i], o);
        }
    }
    if (t4 == 0) {
        #pragma unroll
        for (int i = 0; i < 4; i++) {
            int row = qw * 32 + (i >> 1) * 16 + r8 + (i & 1) * 8;
            atomicMax(&red[row], encf(rmax[i]));
        }
    }
    __syncthreads();
    if (tid < QT) g_chunkmax[(q0 + tid) * NCHUNK + chunk] = red[tid];
}

// ---------------- K2: filter GEMM pass B -> collect hits (smem-buffered) -----
__global__ void __launch_bounds__(256, 2) k_affB(const float* __restrict__ qk) {
    extern __shared__ char sm[];
    __nv_bfloat16* qkb = (__nv_bfloat16*)(sm + SB_QKB);
    int* scnt = (int*)(sm + SB_SCNT);
    int* sbuf = (int*)(sm + SB_SBUF);
    const uint32_t sbase = (uint32_t)__cvta_generic_to_shared(sm);

    const int tid = threadIdx.x, lane = tid & 31, wid = tid >> 5;
    const int qw = wid >> 1, mw = wid & 1;
    const int r8 = lane >> 2, t4 = lane & 3;
    const int q0 = blockIdx.x * QT;
    const int chunk = blockIdx.y;
    const int mc0 = chunk * CHUNKP;

    STAGE_QKB();
    if (tid < QT) scnt[tid] = 0;

    #pragma unroll
    for (int s = 0; s < NSTAGE - 1; s++) {
        STAGE_B_ASYNC(s, mc0 + s * MTILE);
        CP_COMMIT();
    }

    // inline per-q thresholds (3rd-smallest encoded = 20th-largest chunk max)
    float T[4];
    int qg[4], rl[4];
    #pragma unroll
    for (int i = 0; i < 4; i++) {
        rl[i] = qw * 32 + (i >> 1) * 16 + r8 + (i & 1) * 8;
        qg[i] = q0 + rl[i];
        if (qg[i] < QD) {
            unsigned s1 = 0xFFFFFFFFu, s2 = 0xFFFFFFFFu, s3 = 0xFFFFFFFFu;
            const unsigned* cm = &g_chunkmax[qg[i] * NCHUNK];
            #pragma unroll
            for (int c = 0; c < NCHUNK; c++) {
                unsigned u = cm[c];
                if (u < s1)      { s3 = s2; s2 = s1; s1 = u; }
                else if (u < s2) { s3 = s2; s2 = u; }
                else if (u < s3) { s3 = u; }
            }
            T[i] = decf(s3) - 0.0625f;
        } else {
            T[i] = 3.4e38f;
        }
    }
    __syncthreads();

    uint32_t afr[2][4][4];
    LOAD_AFR();

    for (int it = 0; it < ITERS1; it++) {
        const int s = it & (NSTAGE - 1);
        const int m_base = mc0 + it * MTILE;
        CP_WAIT2();
        __syncthreads();

        float acc[2][4][4];
        #pragma unroll
        for (int i = 0; i < 2; i++)
            #pragma unroll
            for (int j = 0; j < 4; j++)
                #pragma unroll
                for (int e = 0; e < 4; e++) acc[i][j][e] = 0.f;

        DO_MMA(s);

        if (it + NSTAGE - 1 < ITERS1) {
            STAGE_B_ASYNC((it + NSTAGE - 1) & (NSTAGE - 1), mc0 + (it + NSTAGE - 1) * MTILE);
        }
        CP_COMMIT();

        // epilogue: mask-gated hit push into per-q smem buffers
        const float* nq = (const float*)(sm + SB_NASQ + s * 256);
        #pragma unroll
        for (int Mt = 0; Mt < 2; Mt++) {
            #pragma unroll
            for (int Nt = 0; Nt < 4; Nt++) {
                int ml = mw * 32 + Nt * 8 + 2 * t4;
                float2 nn = *(const float2*)&nq[ml];
                float v00 = 0.25f * acc[Mt][Nt][0] + nn.x;
                float v01 = 0.25f * acc[Mt][Nt][1] + nn.y;
                float v10 = 0.25f * acc[Mt][Nt][2] + nn.x;
                float v11 = 0.25f * acc[Mt][Nt][3] + nn.y;
                const int i0 = 2 * Mt, i1 = 2 * Mt + 1;
                unsigned msk = (v00 >= T[i0] ? 1u : 0u) | (v01 >= T[i0] ? 2u : 0u)
                             | (v10 >= T[i1] ? 4u : 0u) | (v11 >= T[i1] ? 8u : 0u);
                if (msk) {   // rare
                    if (msk & 1u) {
                        int p = atomicAdd(&scnt[rl[i0]], 1);
                        if (p < CAP2) sbuf[rl[i0] * CAP2 + p] = m_base + ml;
                        else { int g = atomicAdd(&g_hcnt[qg[i0]], 1);
                               if (g < HCAP) g_hits[(size_t)qg[i0] * HCAP + g] = m_base + ml; }
                    }
                    if (msk & 2u) {
                        int p = atomicAdd(&scnt[rl[i0]], 1);
                        if (p < CAP2) sbuf[rl[i0] * CAP2 + p] = m_base + ml + 1;
                        else { int g = atomicAdd(&g_hcnt[qg[i0]], 1);
                               if (g < HCAP) g_hits[(size_t)qg[i0] * HCAP + g] = m_base + ml + 1; }
                    }
                    if (msk & 4u) {
                        int p = atomicAdd(&scnt[rl[i1]], 1);
                        if (p < CAP2) sbuf[rl[i1] * CAP2 + p] = m_base + ml;
                        else { int g = atomicAdd(&g_hcnt[qg[i1]], 1);
                               if (g < HCAP) g_hits[(size_t)qg[i1] * HCAP + g] = m_base + ml; }
                    }
                    if (msk & 8u) {
                        int p = atomicAdd(&scnt[rl[i1]], 1);
                        if (p < CAP2) sbuf[rl[i1] * CAP2 + p] = m_base + ml + 1;
                        else { int g = atomicAdd(&g_hcnt[qg[i1]], 1);
                               if (g < HCAP) g_hits[(size_t)qg[i1] * HCAP + g] = m_base + ml + 1; }
                    }
                }
            }
        }
    }

    // flush per-q smem buffers to global
    __syncthreads();
    if (tid < QT) {
        int q = q0 + tid;
        if (q < QD) {
            int n = min(scnt[tid], CAP2);
            if (n > 0) {
                int base = atomicAdd(&g_hcnt[q], n);
                for (int i = 0; i < n; i++) {
                    int p = base + i;
                    if (p < HCAP) g_hits[(size_t)q * HCAP + p] = sbuf[tid * CAP2 + i];
                }
            }
        }
    }
}

// ---------------- K3: exact fp32 eval of hits + rank-count top-20 + softmax --
__global__ void k_rescue(const float* __restrict__ qk) {
    __shared__ int   pool[8][HCAP];
    __shared__ float pval[8][HCAP];
    __shared__ float qcol[8][CKD];
    __shared__ float sval[8][TOPK];
    __shared__ int   sidx[8][TOPK];

    int w = threadIdx.x >> 5, lane = threadIdx.x & 31;
    int q = blockIdx.x * 8 + w;
    if (q >= QD) return;

    qcol[w][lane] = qk[lane * QD + q];
    qcol[w][lane + 32] = qk[(lane + 32) * QD + q];
    int cnt = g_hcnt[q];
    if (cnt > HCAP) cnt = HCAP;
    const int* hp = g_hits + (size_t)q * HCAP;
    for (int i = lane; i < cnt; i += 32) pool[w][i] = hp[i];
    __syncwarp();

    for (int i = lane; i < cnt; i += 32) {
        int m = pool[w][i];
        const float4* kr = (const float4*)(g_mktf + (size_t)m * CKD);
        float dot = 0.f;
        #pragma unroll
        for (int c4 = 0; c4 < 16; c4++) {
            float4 kv = kr[c4];
            dot += kv.x * qcol[w][c4 * 4 + 0] + kv.y * qcol[w][c4 * 4 + 1]
                 + kv.z * qcol[w][c4 * 4 + 2] + kv.w * qcol[w][c4 * 4 + 3];
        }
        pval[w][i] = 0.25f * dot + g_nasq[m];
    }
    __syncwarp();

    // rank-count selection (strict total order: val desc, idx asc) — ranks unique
    for (int i = lane; i < cnt; i += 32) {
        float vi = pval[w][i];
        int   ii = pool[w][i];
        int rank = 0;
        for (int j = 0; j < cnt; j++) {
            float vj = pval[w][j];
            int   ij = pool[w][j];
            rank += (vj > vi || (vj == vi && ij < ii)) ? 1 : 0;
        }
        if (rank < TOPK) { sval[w][rank] = vi; sidx[w][rank] = ii; }
    }
    __syncwarp();

    float v = (lane < TOPK) ? sval[w][lane] : -3.4e38f;
    float mx = v;
    #pragma unroll
    for (int s = 16; s > 0; s >>= 1) {
        float o = __shfl_xor_sync(0xffffffffu, mx, s);
        if (o > mx) mx = o;
    }
    float e = (lane < TOPK) ? expf(v - mx) : 0.f;
    float sum = e;
    #pragma unroll
    for (int s = 16; s > 0; s >>= 1) sum += __shfl_xor_sync(0xffffffffu, sum, s);
    if (lane < TOPK) {
        g_wval[q * TOPK + lane] = e / sum;
        g_widx[q * TOPK + lane] = sidx[w][lane];
    }
}

// ---------------- K4: sparse readout (fp16 v, half2 loads) -------------------
__global__ void k_readout(float* __restrict__ out) {
    __shared__ float sw[QT3 * TOPK];
    __shared__ int   si[QT3 * TOPK];
    int q0 = blockIdx.x * QT3;
    int ch2 = blockIdx.y * 256 + threadIdx.x;   // half2 index
    for (int t = threadIdx.x; t < QT3 * TOPK; t += 256) {
        int q = q0 + t / TOPK;
        if (q < QD) {
            sw[t] = g_wval[q * TOPK + (t % TOPK)];
            si[t] = g_widx[q * TOPK + (t % TOPK)];
        } else { sw[t] = 0.f; si[t] = 0; }
    }
    __syncthreads();

    const __half2* vt2 = (const __half2*)g_vth;
    float2 acc[QT3];
    #pragma unroll
    for (int j = 0; j < QT3; j++) acc[j] = make_float2(0.f, 0.f);

    #pragma unroll
    for (int k = 0; k < TOPK; k++) {
        #pragma unroll
        for (int j = 0; j < QT3; j++) {
            float w = sw[j * TOPK + k];
            int   m = si[j * TOPK + k];
            float2 f = __half22float2(vt2[(size_t)m * (CHD / 2) + ch2]);
            acc[j].x += w * f.x;
            acc[j].y += w * f.y;
        }
    }

    int ch0 = ch2 * 2;
    if (q0 + QT3 <= QD) {
        float4* o0 = (float4*)(out + (size_t)ch0 * QD + q0);
        float4* o1 = (float4*)(out + (size_t)(ch0 + 1) * QD + q0);
        #pragma unroll
        for (int jj = 0; jj < QT3 / 4; jj++) {
            o0[jj] = make_float4(acc[jj*4].x, acc[jj*4+1].x, acc[jj*4+2].x, acc[jj*4+3].x);
            o1[jj] = make_float4(acc[jj*4].y, acc[jj*4+1].y, acc[jj*4+2].y, acc[jj*4+3].y);
        }
    } else {
        #pragma unroll
        for (int j = 0; j < QT3; j++) {
            int q = q0 + j;
            if (q < QD) {
                out[(size_t)ch0 * QD + q] = acc[j].x;
                out[(size_t)(ch0 + 1) * QD + q] = acc[j].y;
            }
        }
    }
}

// ---------------- launch ----------------
extern "C" void kernel_launch(void* const* d_in, const int* in_sizes, int n_in,
                              void* d_out, int out_size) {
    const float* qk = (const float*)d_in[0];   // [64][1620]
    const float* mk = (const float*)d_in[1];   // [64][32400]
    const float* mv = (const float*)d_in[2];   // [1536][32400]
    float* out = (float*)d_out;                // [1536][1620]
    (void)in_sizes; (void)n_in; (void)out_size;

    k_prep<<<MPAD / 32, 256>>>(mk);                                          // 1

    cudaFuncSetAttribute(k_affA, cudaFuncAttributeMaxDynamicSharedMemorySize, SB_TOTAL);
    cudaFuncSetAttribute(k_affB, cudaFuncAttributeMaxDynamicSharedMemorySize, SB_TOTAL2);
    k_affA<<<dim3(NQB, NCHUNK), 256, SB_TOTAL>>>(qk);                        // 2

    k_transpose<<<dim3((MD + 31) / 32, CHD / 32), dim3(32, 8)>>>(mv);        // 3

    k_affB<<<dim3(NQB, NCHUNK), 256, SB_TOTAL2>>>(qk);                       // 4 (ncu slot)
    k_rescue<<<(QD + 7) / 8, 256>>>(qk);                                     // 5
    k_readout<<<dim3((QD + QT3 - 1) / QT3, CHD / 512), 256>>>(out);          // 6
}

// round 15
// speedup vs baseline: 1.2334x; 1.0064x over previous
#include <cuda_runtime.h>
#include <cuda_bf16.h>
#include <cuda_fp16.h>
#include <math.h>
#include <stdint.h>

// ---------------- problem constants ----------------
#define CKD 64
#define QD 1620          // H*W
#define MD 32400
#define TOPK 20
#define CHD 1536         // OD*CVD

// ---------------- filter tiling ----------------
#define QT 128           // q per block
#define MTILE 64         // m per iteration
#define NQB 13           // 13*128 = 1664 >= 1620
#define NCHUNK 22
#define CHUNKP 1536      // m per chunk
#define ITERS1 24        // CHUNKP / MTILE
#define MPAD (NCHUNK * CHUNKP)   // 33792
#define HCAP 512         // per-q global hit capacity
#define CAP2 16          // per-(q,chunk) smem hit buffer capacity
#define NSTAGE 4
#define QT3 16

// ---------------- device scratch ----------------
__device__ __align__(16) float g_nasq[MPAD];
__device__ __align__(16) __nv_bfloat16 g_mkt[(size_t)MPAD * CKD];
__device__ __align__(16) float g_mktf[(size_t)MD * CKD];
__device__ __align__(16) __half g_vth[(size_t)MD * CHD];
__device__ unsigned g_chunkmax[NQB * QT * NCHUNK];
__device__ int   g_hcnt[QD];
__device__ int   g_hits[(size_t)QD * HCAP];
__device__ float g_wval[QD * TOPK];
__device__ int   g_widx[QD * TOPK];

// order-preserving float<->uint map (unsigned domain)
__device__ __forceinline__ unsigned encf(float v) {
    unsigned b = __float_as_uint(v);
    return (b & 0x80000000u) ? ~b : (b | 0x80000000u);
}
__device__ __forceinline__ float decf(unsigned u) {
    unsigned b = (u & 0x80000000u) ? (u & 0x7FFFFFFFu) : ~u;
    return __uint_as_float(b);
}

// ---------------- async copy helpers ----------------
#define CP_ASYNC16(dst, src) \
    asm volatile("cp.async.cg.shared.global [%0], [%1], 16;" :: "r"(dst), "l"(src))
#define CP_COMMIT() asm volatile("cp.async.commit_group;")
#define CP_WAIT2()  asm volatile("cp.async.wait_group 2;" ::: "memory")

// ---------------- mma helper ----------------
__device__ __forceinline__ void mma_bf16(float* c, const uint32_t* a,
                                         uint32_t b0, uint32_t b1) {
    asm volatile(
        "mma.sync.aligned.m16n8k16.row.col.f32.bf16.bf16.f32 "
        "{%0,%1,%2,%3}, {%4,%5,%6,%7}, {%8,%9}, {%0,%1,%2,%3};"
        : "+f"(c[0]), "+f"(c[1]), "+f"(c[2]), "+f"(c[3])
        : "r"(a[0]), "r"(a[1]), "r"(a[2]), "r"(a[3]), "r"(b0), "r"(b1));
}

// ---------------- K0: prep — mk transpose (bf16+fp32) + nasq + hcnt zero -----
__global__ void __launch_bounds__(256) k_prep(const float* __restrict__ mk) {
    __shared__ float tile[CKD][33];
    const int m0 = blockIdx.x * 32;
    const int tid = threadIdx.x;

    int gz = blockIdx.x * 256 + tid;
    if (gz < QD) g_hcnt[gz] = 0;

    {
        int ml = tid & 31;
        int m = m0 + ml;
        #pragma unroll
        for (int i = 0; i < 8; i++) {
            int c = (tid >> 5) + i * 8;
            tile[c][ml] = (m < MD) ? mk[(size_t)c * MD + m] : 0.f;
        }
    }
    __syncthreads();

    #pragma unroll
    for (int i = 0; i < 8; i++) {
        int idx = tid + i * 256;
        int ml = idx >> 6, c = idx & 63;
        float v = tile[c][ml];
        int m = m0 + ml;
        g_mkt[(size_t)m * CKD + c] = __float2bfloat16(v);
        if (m < MD) g_mktf[(size_t)m * CKD + c] = v;
    }

    if (tid < 32) {
        int m = m0 + tid;
        float s = 0.f;
        #pragma unroll
        for (int c = 0; c < CKD; c++) {
            float v = tile[c][tid];
            s += v * v;
        }
        g_nasq[m] = (m < MD) ? -(s * 0.125f) : -1.0e37f;
    }
}

// ---------------- KT: mem_v transpose [1536][M] -> fp16 [M][1536] ------------
__global__ void k_transpose(const float* __restrict__ v) {
    __shared__ float tile[32][33];
    int m0 = blockIdx.x * 32, c0 = blockIdx.y * 32;
    int tx = threadIdx.x, ty = threadIdx.y;
    #pragma unroll
    for (int i = ty; i < 32; i += 8) {
        int m = m0 + tx;
        tile[i][tx] = (m < MD) ? v[(size_t)(c0 + i) * MD + m] : 0.f;
    }
    __syncthreads();
    #pragma unroll
    for (int i = ty; i < 32; i += 8) {
        int m = m0 + i;
        if (m < MD) g_vth[(size_t)m * CHD + c0 + tx] = __float2half(tile[tx][i]);
    }
}

// ---------------- filter GEMM common smem layout (bytes) ----------------
#define SB_QKB   0                       // bf16 qk [128][68] = 17408
#define SB_B     17408                   // NSTAGE x (64 rows x 144B) = 36864
#define SB_NASQ  54272                   // NSTAGE x 256B = 1024
#define SB_RED   55296                   // 128 unsigned = 512 (affA)
#define SB_TOTAL 55808
// affB extras
#define SB_SCNT  55296                   // 128 int = 512
#define SB_SBUF  55808                   // 128 x CAP2 int = 8192
#define SB_TOTAL2 64000

#define STAGE_B_ASYNC(s, mb) do { \
    const char* _gs = (const char*)g_mkt + (size_t)(mb) * (CKD * 2); \
    uint32_t _bb = sbase + SB_B + (s) * 9216; \
    _Pragma("unroll") \
    for (int _i = 0; _i < 2; _i++) { \
        int _idx = tid + _i * 256; \
        int _m = _idx >> 3, _c16 = _idx & 7; \
        CP_ASYNC16(_bb + _m * 144 + _c16 * 16, _gs + _m * 128 + _c16 * 16); \
    } \
    if (tid < 16) \
        CP_ASYNC16(sbase + SB_NASQ + (s) * 256 + tid * 16, \
                   (const char*)g_nasq + (size_t)(mb) * 4 + tid * 16); \
} while (0)

#define STAGE_QKB() do { \
    for (int t = tid; t < CKD * QT; t += 256) { \
        int c = t >> 7, j = t & 127; \
        int q = q0 + j; \
        float v = (q < QD) ? qk[c * QD + q] : 0.f; \
        qkb[j * 68 + c] = __float2bfloat16(v); \
    } \
} while (0)

#define LOAD_AFR() do { \
    _Pragma("unroll") \
    for (int Mt = 0; Mt < 2; Mt++) { \
        _Pragma("unroll") \
        for (int ks = 0; ks < 4; ks++) { \
            int qr = qw * 32 + Mt * 16 + r8; \
            int cc = ks * 16 + 2 * t4; \
            afr[Mt][ks][0] = *(const uint32_t*)&qkb[qr * 68 + cc]; \
            afr[Mt][ks][1] = *(const uint32_t*)&qkb[(qr + 8) * 68 + cc]; \
            afr[Mt][ks][2] = *(const uint32_t*)&qkb[qr * 68 + cc + 8]; \
            afr[Mt][ks][3] = *(const uint32_t*)&qkb[(qr + 8) * 68 + cc + 8]; \
        } \
    } \
} while (0)

#define DO_MMA(s) do { \
    const uint32_t* Bb = (const uint32_t*)(sm + SB_B + (s) * 9216); \
    _Pragma("unroll") \
    for (int ks = 0; ks < 4; ks++) { \
        _Pragma("unroll") \
        for (int Nt = 0; Nt < 4; Nt++) { \
            int nl = mw * 32 + Nt * 8 + r8; \
            uint32_t b0 = Bb[nl * 36 + ks * 8 + t4]; \
            uint32_t b1 = Bb[nl * 36 + ks * 8 + t4 + 4]; \
            mma_bf16(acc[0][Nt], afr[0][ks], b0, b1); \
            mma_bf16(acc[1][Nt], afr[1][ks], b0, b1); \
        } \
    } \
} while (0)

// ---------------- K1: filter GEMM pass A -> per-(q,chunk) max ----------------
__global__ void __launch_bounds__(256, 2) k_affA(const float* __restrict__ qk) {
    extern __shared__ char sm[];
    __nv_bfloat16* qkb = (__nv_bfloat16*)(sm + SB_QKB);
    unsigned* red = (unsigned*)(sm + SB_RED);
    const uint32_t sbase = (uint32_t)__cvta_generic_to_shared(sm);

    const int tid = threadIdx.x, lane = tid & 31, wid = tid >> 5;
    const int qw = wid >> 1, mw = wid & 1;
    const int r8 = lane >> 2, t4 = lane & 3;
    const int q0 = blockIdx.x * QT;
    const int chunk = blockIdx.y;
    const int mc0 = chunk * CHUNKP;

    STAGE_QKB();
    if (tid < QT) red[tid] = 0u;

    #pragma unroll
    for (int s = 0; s < NSTAGE - 1; s++) {
        STAGE_B_ASYNC(s, mc0 + s * MTILE);
        CP_COMMIT();
    }
    __syncthreads();

    uint32_t afr[2][4][4];
    LOAD_AFR();

    float rmax[4] = {-3.0e38f, -3.0e38f, -3.0e38f, -3.0e38f};

    for (int it = 0; it < ITERS1; it++) {
        const int s = it & (NSTAGE - 1);
        CP_WAIT2();
        __syncthreads();

        float acc[2][4][4];
        #pragma unroll
        for (int i = 0; i < 2; i++)
            #pragma unroll
            for (int j = 0; j < 4; j++)
                #pragma unroll
                for (int e = 0; e < 4; e++) acc[i][j][e] = 0.f;

        DO_MMA(s);

        if (it + NSTAGE - 1 < ITERS1) {
            STAGE_B_ASYNC((it + NSTAGE - 1) & (NSTAGE - 1), mc0 + (it + NSTAGE - 1) * MTILE);
        }
        CP_COMMIT();

        const float* nq = (const float*)(sm + SB_NASQ + s * 256);
        #pragma unroll
        for (int Mt = 0; Mt < 2; Mt++) {
            #pragma unroll
            for (int Nt = 0; Nt < 4; Nt++) {
                int ml = mw * 32 + Nt * 8 + 2 * t4;
                float2 nn = *(const float2*)&nq[ml];
                float a0 = fmaxf(0.25f * acc[Mt][Nt][0] + nn.x, 0.25f * acc[Mt][Nt][1] + nn.y);
                float a1 = fmaxf(0.25f * acc[Mt][Nt][2] + nn.x, 0.25f * acc[Mt][Nt][3] + nn.y);
                rmax[2 * Mt + 0] = fmaxf(rmax[2 * Mt + 0], a0);
                rmax[2 * Mt + 1] = fmaxf(rmax[2 * Mt + 1], a1);
            }
        }
    }

    #pragma unroll
    for (int i = 0; i < 4; i++) {
        #pragma unroll
        for (int s2 = 1; s2 <= 2; s2 <<= 1) {
            float o = __shfl_xor_sync(0xffffffffu, rmax[i], s2);
            rmax[i] = fmaxf(rmax[i], o);
        }
    }
    if (t4 == 0) {
        #pragma unroll
        for (int i = 0; i < 4; i++) {
            int row = qw * 32 + (i >> 1) * 16 + r8 + (i & 1) * 8;
            atomicMax(&red[row], encf(rmax[i]));
        }
    }
    __syncthreads();
    if (tid < QT) g_chunkmax[(q0 + tid) * NCHUNK + chunk] = red[tid];
}

// ---------------- K2: filter GEMM pass B -> collect hits (smem-buffered) -----
__global__ void __launch_bounds__(256, 2) k_affB(const float* __restrict__ qk) {
    extern __shared__ char sm[];
    __nv_bfloat16* qkb = (__nv_bfloat16*)(sm + SB_QKB);
    int* scnt = (int*)(sm + SB_SCNT);
    int* sbuf = (int*)(sm + SB_SBUF);
    const uint32_t sbase = (uint32_t)__cvta_generic_to_shared(sm);

    const int tid = threadIdx.x, lane = tid & 31, wid = tid >> 5;
    const int qw = wid >> 1, mw = wid & 1;
    const int r8 = lane >> 2, t4 = lane & 3;
    const int q0 = blockIdx.x * QT;
    const int chunk = blockIdx.y;
    const int mc0 = chunk * CHUNKP;

    STAGE_QKB();
    if (tid < QT) scnt[tid] = 0;

    #pragma unroll
    for (int s = 0; s < NSTAGE - 1; s++) {
        STAGE_B_ASYNC(s, mc0 + s * MTILE);
        CP_COMMIT();
    }

    // inline per-q thresholds (3rd-smallest encoded = 20th-largest chunk max)
    float T[4];
    int qg[4], rl[4];
    #pragma unroll
    for (int i = 0; i < 4; i++) {
        rl[i] = qw * 32 + (i >> 1) * 16 + r8 + (i & 1) * 8;
        qg[i] = q0 + rl[i];
        if (qg[i] < QD) {
            unsigned s1 = 0xFFFFFFFFu, s2 = 0xFFFFFFFFu, s3 = 0xFFFFFFFFu;
            const unsigned* cm = &g_chunkmax[qg[i] * NCHUNK];
            #pragma unroll
            for (int c = 0; c < NCHUNK; c++) {
                unsigned u = cm[c];
                if (u < s1)      { s3 = s2; s2 = s1; s1 = u; }
                else if (u < s2) { s3 = s2; s2 = u; }
                else if (u < s3) { s3 = u; }
            }
            T[i] = decf(s3) - 0.0625f;
        } else {
            T[i] = 3.4e38f;
        }
    }
    __syncthreads();

    uint32_t afr[2][4][4];
    LOAD_AFR();

    for (int it = 0; it < ITERS1; it++) {
        const int s = it & (NSTAGE - 1);
        const int m_base = mc0 + it * MTILE;
        CP_WAIT2();
        __syncthreads();

        float acc[2][4][4];
        #pragma unroll
        for (int i = 0; i < 2; i++)
            #pragma unroll
            for (int j = 0; j < 4; j++)
                #pragma unroll
                for (int e = 0; e < 4; e++) acc[i][j][e] = 0.f;

        DO_MMA(s);

        if (it + NSTAGE - 1 < ITERS1) {
            STAGE_B_ASYNC((it + NSTAGE - 1) & (NSTAGE - 1), mc0 + (it + NSTAGE - 1) * MTILE);
        }
        CP_COMMIT();

        // epilogue: warp-uniform-gated hit push into per-q smem buffers
        const float* nq = (const float*)(sm + SB_NASQ + s * 256);
        #pragma unroll
        for (int Mt = 0; Mt < 2; Mt++) {
            #pragma unroll
            for (int Nt = 0; Nt < 4; Nt++) {
                int ml = mw * 32 + Nt * 8 + 2 * t4;
                float2 nn = *(const float2*)&nq[ml];
                float v00 = 0.25f * acc[Mt][Nt][0] + nn.x;
                float v01 = 0.25f * acc[Mt][Nt][1] + nn.y;
                float v10 = 0.25f * acc[Mt][Nt][2] + nn.x;
                float v11 = 0.25f * acc[Mt][Nt][3] + nn.y;
                const int i0 = 2 * Mt, i1 = 2 * Mt + 1;
                unsigned msk = (v00 >= T[i0] ? 1u : 0u) | (v01 >= T[i0] ? 2u : 0u)
                             | (v10 >= T[i1] ? 4u : 0u) | (v11 >= T[i1] ? 8u : 0u);
                if (__any_sync(0xffffffffu, msk != 0u)) {   // warp-uniform, rarely taken
                    if (msk & 1u) {
                        int p = atomicAdd(&scnt[rl[i0]], 1);
                        if (p < CAP2) sbuf[rl[i0] * CAP2 + p] = m_base + ml;
                        else { int g = atomicAdd(&g_hcnt[qg[i0]], 1);
                               if (g < HCAP) g_hits[(size_t)qg[i0] * HCAP + g] = m_base + ml; }
                    }
                    if (msk & 2u) {
                        int p = atomicAdd(&scnt[rl[i0]], 1);
                        if (p < CAP2) sbuf[rl[i0] * CAP2 + p] = m_base + ml + 1;
                        else { int g = atomicAdd(&g_hcnt[qg[i0]], 1);
                               if (g < HCAP) g_hits[(size_t)qg[i0] * HCAP + g] = m_base + ml + 1; }
                    }
                    if (msk & 4u) {
                        int p = atomicAdd(&scnt[rl[i1]], 1);
                        if (p < CAP2) sbuf[rl[i1] * CAP2 + p] = m_base + ml;
                        else { int g = atomicAdd(&g_hcnt[qg[i1]], 1);
                               if (g < HCAP) g_hits[(size_t)qg[i1] * HCAP + g] = m_base + ml; }
                    }
                    if (msk & 8u) {
                        int p = atomicAdd(&scnt[rl[i1]], 1);
                        if (p < CAP2) sbuf[rl[i1] * CAP2 + p] = m_base + ml + 1;
                        else { int g = atomicAdd(&g_hcnt[qg[i1]], 1);
                               if (g < HCAP) g_hits[(size_t)qg[i1] * HCAP + g] = m_base + ml + 1; }
                    }
                }
            }
        }
    }

    // flush per-q smem buffers to global
    __syncthreads();
    if (tid < QT) {
        int q = q0 + tid;
        if (q < QD) {
            int n = min(scnt[tid], CAP2);
            if (n > 0) {
                int base = atomicAdd(&g_hcnt[q], n);
                for (int i = 0; i < n; i++) {
                    int p = base + i;
                    if (p < HCAP) g_hits[(size_t)q * HCAP + p] = sbuf[tid * CAP2 + i];
                }
            }
        }
    }
}

// ---------------- K3: exact fp32 eval of hits + rank-count top-20 + softmax --
__global__ void k_rescue(const float* __restrict__ qk) {
    __shared__ int   pool[8][HCAP];
    __shared__ float pval[8][HCAP];
    __shared__ float qcol[8][CKD];
    __shared__ float sval[8][TOPK];
    __shared__ int   sidx[8][TOPK];

    int w = threadIdx.x >> 5, lane = threadIdx.x & 31;
    int q = blockIdx.x * 8 + w;
    if (q >= QD) return;

    qcol[w][lane] = qk[lane * QD + q];
    qcol[w][lane + 32] = qk[(lane + 32) * QD + q];
    int cnt = g_hcnt[q];
    if (cnt > HCAP) cnt = HCAP;
    const int* hp = g_hits + (size_t)q * HCAP;
    for (int i = lane; i < cnt; i += 32) pool[w][i] = hp[i];
    __syncwarp();

    for (int i = lane; i < cnt; i += 32) {
        int m = pool[w][i];
        const float4* kr = (const float4*)(g_mktf + (size_t)m * CKD);
        float dot = 0.f;
        #pragma unroll
        for (int c4 = 0; c4 < 16; c4++) {
            float4 kv = kr[c4];
            dot += kv.x * qcol[w][c4 * 4 + 0] + kv.y * qcol[w][c4 * 4 + 1]
                 + kv.z * qcol[w][c4 * 4 + 2] + kv.w * qcol[w][c4 * 4 + 3];
        }
        pval[w][i] = 0.25f * dot + g_nasq[m];
    }
    __syncwarp();

    // rank-count selection (strict total order: val desc, idx asc) — ranks unique
    for (int i = lane; i < cnt; i += 32) {
        float vi = pval[w][i];
        int   ii = pool[w][i];
        int rank = 0;
        for (int j = 0; j < cnt; j++) {
            float vj = pval[w][j];
            int   ij = pool[w][j];
            rank += (vj > vi || (vj == vi && ij < ii)) ? 1 : 0;
        }
        if (rank < TOPK) { sval[w][rank] = vi; sidx[w][rank] = ii; }
    }
    __syncwarp();

    float v = (lane < TOPK) ? sval[w][lane] : -3.4e38f;
    float mx = v;
    #pragma unroll
    for (int s = 16; s > 0; s >>= 1) {
        float o = __shfl_xor_sync(0xffffffffu, mx, s);
        if (o > mx) mx = o;
    }
    float e = (lane < TOPK) ? expf(v - mx) : 0.f;
    float sum = e;
    #pragma unroll
    for (int s = 16; s > 0; s >>= 1) sum += __shfl_xor_sync(0xffffffffu, sum, s);
    if (lane < TOPK) {
        g_wval[q * TOPK + lane] = e / sum;
        g_widx[q * TOPK + lane] = sidx[w][lane];
    }
}

// ---------------- K4: sparse readout (fp16 v, half2 loads) -------------------
__global__ void k_readout(float* __restrict__ out) {
    __shared__ float sw[QT3 * TOPK];
    __shared__ int   si[QT3 * TOPK];
    int q0 = blockIdx.x * QT3;
    int ch2 = blockIdx.y * 256 + threadIdx.x;   // half2 index
    for (int t = threadIdx.x; t < QT3 * TOPK; t += 256) {
        int q = q0 + t / TOPK;
        if (q < QD) {
            sw[t] = g_wval[q * TOPK + (t % TOPK)];
            si[t] = g_widx[q * TOPK + (t % TOPK)];
        } else { sw[t] = 0.f; si[t] = 0; }
    }
    __syncthreads();

    const __half2* vt2 = (const __half2*)g_vth;
    float2 acc[QT3];
    #pragma unroll
    for (int j = 0; j < QT3; j++) acc[j] = make_float2(0.f, 0.f);

    #pragma unroll
    for (int k = 0; k < TOPK; k++) {
        #pragma unroll
        for (int j = 0; j < QT3; j++) {
            float w = sw[j * TOPK + k];
            int   m = si[j * TOPK + k];
            float2 f = __half22float2(vt2[(size_t)m * (CHD / 2) + ch2]);
            acc[j].x += w * f.x;
            acc[j].y += w * f.y;
        }
    }

    int ch0 = ch2 * 2;
    if (q0 + QT3 <= QD) {
        float4* o0 = (float4*)(out + (size_t)ch0 * QD + q0);
        float4* o1 = (float4*)(out + (size_t)(ch0 + 1) * QD + q0);
        #pragma unroll
        for (int jj = 0; jj < QT3 / 4; jj++) {
            o0[jj] = make_float4(acc[jj*4].x, acc[jj*4+1].x, acc[jj*4+2].x, acc[jj*4+3].x);
            o1[jj] = make_float4(acc[jj*4].y, acc[jj*4+1].y, acc[jj*4+2].y, acc[jj*4+3].y);
        }
    } else {
        #pragma unroll
        for (int j = 0; j < QT3; j++) {
            int q = q0 + j;
            if (q < QD) {
                out[(size_t)ch0 * QD + q] = acc[j].x;
                out[(size_t)(ch0 + 1) * QD + q] = acc[j].y;
            }
        }
    }
}

// ---------------- launch ----------------
extern "C" void kernel_launch(void* const* d_in, const int* in_sizes, int n_in,
                              void* d_out, int out_size) {
    const float* qk = (const float*)d_in[0];   // [64][1620]
    const float* mk = (const float*)d_in[1];   // [64][32400]
    const float* mv = (const float*)d_in[2];   // [1536][32400]
    float* out = (float*)d_out;                // [1536][1620]
    (void)in_sizes; (void)n_in; (void)out_size;

    k_prep<<<MPAD / 32, 256>>>(mk);                                          // 1

    cudaFuncSetAttribute(k_affA, cudaFuncAttributeMaxDynamicSharedMemorySize, SB_TOTAL);
    cudaFuncSetAttribute(k_affB, cudaFuncAttributeMaxDynamicSharedMemorySize, SB_TOTAL2);
    k_affA<<<dim3(NQB, NCHUNK), 256, SB_TOTAL>>>(qk);                        // 2
    k_affB<<<dim3(NQB, NCHUNK), 256, SB_TOTAL2>>>(qk);                       // 3

    k_rescue<<<(QD + 7) / 8, 256>>>(qk);                                     // 4 (ncu slot)

    k_transpose<<<dim3((MD + 31) / 32, CHD / 32), dim3(32, 8)>>>(mv);        // 5
    k_readout<<<dim3((QD + QT3 - 1) / QT3, CHD / 512), 256>>>(out);          // 6
}

// round 16
// speedup vs baseline: 1.6896x; 1.3699x over previous
#include <cuda_runtime.h>
#include <cuda_bf16.h>
#include <cuda_fp16.h>
#include <math.h>
#include <stdint.h>

// ---------------- problem constants ----------------
#define CKD 64
#define QD 1620          // H*W
#define MD 32400
#define TOPK 20
#define CHD 1536         // OD*CVD

// ---------------- filter tiling ----------------
#define QT 128           // q per block
#define MTILE 64         // m per iteration
#define NQB 13           // 13*128 = 1664 >= 1620
#define NCHUNK 22
#define CHUNKP 1536      // m per chunk
#define ITERS1 24        // CHUNKP / MTILE
#define MPAD (NCHUNK * CHUNKP)   // 33792
#define HCAP 512         // per-q global hit capacity
#define CAP2 16          // per-(q,chunk) smem hit buffer capacity
#define NSTAGE 4
#define QT3 16

// ---------------- device scratch ----------------
__device__ __align__(16) float g_nasq[MPAD];
__device__ __align__(16) __nv_bfloat16 g_mkt[(size_t)MPAD * CKD];
__device__ __align__(16) float g_mktf[(size_t)MD * CKD];
__device__ __align__(16) __half g_vth[(size_t)MD * CHD];
__device__ unsigned g_chunkmax[NQB * QT * NCHUNK];
__device__ int   g_hcnt[QD];
__device__ int   g_hits[(size_t)QD * HCAP];
__device__ float g_wval[QD * TOPK];
__device__ int   g_widx[QD * TOPK];

// order-preserving float<->uint map (unsigned domain)
__device__ __forceinline__ unsigned encf(float v) {
    unsigned b = __float_as_uint(v);
    return (b & 0x80000000u) ? ~b : (b | 0x80000000u);
}
__device__ __forceinline__ float decf(unsigned u) {
    unsigned b = (u & 0x80000000u) ? (u & 0x7FFFFFFFu) : ~u;
    return __uint_as_float(b);
}

// ---------------- async copy helpers ----------------
#define CP_ASYNC16(dst, src) \
    asm volatile("cp.async.cg.shared.global [%0], [%1], 16;" :: "r"(dst), "l"(src))
#define CP_COMMIT() asm volatile("cp.async.commit_group;")
#define CP_WAIT2()  asm volatile("cp.async.wait_group 2;" ::: "memory")

// ---------------- mma helper ----------------
__device__ __forceinline__ void mma_bf16(float* c, const uint32_t* a,
                                         uint32_t b0, uint32_t b1) {
    asm volatile(
        "mma.sync.aligned.m16n8k16.row.col.f32.bf16.bf16.f32 "
        "{%0,%1,%2,%3}, {%4,%5,%6,%7}, {%8,%9}, {%0,%1,%2,%3};"
        : "+f"(c[0]), "+f"(c[1]), "+f"(c[2]), "+f"(c[3])
        : "r"(a[0]), "r"(a[1]), "r"(a[2]), "r"(a[3]), "r"(b0), "r"(b1));
}

// ---------------- K0: prep — mk transpose (bf16+fp32) + nasq + hcnt zero -----
__global__ void __launch_bounds__(256) k_prep(const float* __restrict__ mk) {
    __shared__ float tile[CKD][33];
    const int m0 = blockIdx.x * 32;
    const int tid = threadIdx.x;

    int gz = blockIdx.x * 256 + tid;
    if (gz < QD) g_hcnt[gz] = 0;

    {
        int ml = tid & 31;
        int m = m0 + ml;
        #pragma unroll
        for (int i = 0; i < 8; i++) {
            int c = (tid >> 5) + i * 8;
            tile[c][ml] = (m < MD) ? mk[(size_t)c * MD + m] : 0.f;
        }
    }
    __syncthreads();

    #pragma unroll
    for (int i = 0; i < 8; i++) {
        int idx = tid + i * 256;
        int ml = idx >> 6, c = idx & 63;
        float v = tile[c][ml];
        int m = m0 + ml;
        g_mkt[(size_t)m * CKD + c] = __float2bfloat16(v);
        if (m < MD) g_mktf[(size_t)m * CKD + c] = v;
    }

    if (tid < 32) {
        int m = m0 + tid;
        float s = 0.f;
        #pragma unroll
        for (int c = 0; c < CKD; c++) {
            float v = tile[c][tid];
            s += v * v;
        }
        g_nasq[m] = (m < MD) ? -(s * 0.125f) : -1.0e37f;
    }
}

// ---------------- KT: mem_v transpose [1536][M] -> fp16 [M][1536] ------------
// 32m x 64c tile: conflict-free reads (69-pad), half2 128B-row writes
__global__ void __launch_bounds__(256) k_transpose(const float* __restrict__ v) {
    __shared__ float tile[32][69];
    const int m0 = blockIdx.x * 32;
    const int c0 = blockIdx.y * 64;
    const int tid = threadIdx.x;
    const int ml = tid & 31, cs = tid >> 5;

    #pragma unroll
    for (int i = 0; i < 8; i++) {
        int c = cs + i * 8;                   // 0..63
        int m = m0 + ml;
        tile[ml][c] = (m < MD) ? v[(size_t)(c0 + c) * MD + m] : 0.f;
    }
    __syncthreads();

    const int cl = (tid & 31) * 2, r8 = tid >> 5;
    #pragma unroll
    for (int i = 0; i < 4; i++) {
        int r = r8 + i * 8;
        int m = m0 + r;
        if (m < MD) {
            __half2 h = __floats2half2_rn(tile[r][cl], tile[r][cl + 1]);
            *(__half2*)(&g_vth[(size_t)m * CHD + c0 + cl]) = h;
        }
    }
}

// ---------------- filter GEMM common smem layout (bytes) ----------------
#define SB_QKB   0                       // bf16 qk [128][68] = 17408
#define SB_B     17408                   // NSTAGE x (64 rows x 144B) = 36864
#define SB_NASQ  54272                   // NSTAGE x 256B = 1024
#define SB_RED   55296                   // 128 unsigned = 512 (affA)
#define SB_TOTAL 55808
// affB extras
#define SB_SCNT  55296                   // 128 int = 512
#define SB_SBUF  55808                   // 128 x CAP2 int = 8192
#define SB_TOTAL2 64000

#define STAGE_B_ASYNC(s, mb) do { \
    const char* _gs = (const char*)g_mkt + (size_t)(mb) * (CKD * 2); \
    uint32_t _bb = sbase + SB_B + (s) * 9216; \
    _Pragma("unroll") \
    for (int _i = 0; _i < 2; _i++) { \
        int _idx = tid + _i * 256; \
        int _m = _idx >> 3, _c16 = _idx & 7; \
        CP_ASYNC16(_bb + _m * 144 + _c16 * 16, _gs + _m * 128 + _c16 * 16); \
    } \
    if (tid < 16) \
        CP_ASYNC16(sbase + SB_NASQ + (s) * 256 + tid * 16, \
                   (const char*)g_nasq + (size_t)(mb) * 4 + tid * 16); \
} while (0)

#define STAGE_QKB() do { \
    for (int t = tid; t < CKD * QT; t += 256) { \
        int c = t >> 7, j = t & 127; \
        int q = q0 + j; \
        float v = (q < QD) ? qk[c * QD + q] : 0.f; \
        qkb[j * 68 + c] = __float2bfloat16(v); \
    } \
} while (0)

#define LOAD_AFR() do { \
    _Pragma("unroll") \
    for (int Mt = 0; Mt < 2; Mt++) { \
        _Pragma("unroll") \
        for (int ks = 0; ks < 4; ks++) { \
            int qr = qw * 32 + Mt * 16 + r8; \
            int cc = ks * 16 + 2 * t4; \
            afr[Mt][ks][0] = *(const uint32_t*)&qkb[qr * 68 + cc]; \
            afr[Mt][ks][1] = *(const uint32_t*)&qkb[(qr + 8) * 68 + cc]; \
            afr[Mt][ks][2] = *(const uint32_t*)&qkb[qr * 68 + cc + 8]; \
            afr[Mt][ks][3] = *(const uint32_t*)&qkb[(qr + 8) * 68 + cc + 8]; \
        } \
    } \
} while (0)

#define DO_MMA(s) do { \
    const uint32_t* Bb = (const uint32_t*)(sm + SB_B + (s) * 9216); \
    _Pragma("unroll") \
    for (int ks = 0; ks < 4; ks++) { \
        _Pragma("unroll") \
        for (int Nt = 0; Nt < 4; Nt++) { \
            int nl = mw * 32 + Nt * 8 + r8; \
            uint32_t b0 = Bb[nl * 36 + ks * 8 + t4]; \
            uint32_t b1 = Bb[nl * 36 + ks * 8 + t4 + 4]; \
            mma_bf16(acc[0][Nt], afr[0][ks], b0, b1); \
            mma_bf16(acc[1][Nt], afr[1][ks], b0, b1); \
        } \
    } \
} while (0)

// ---------------- K1: filter GEMM pass A -> per-(q,chunk) max ----------------
__global__ void __launch_bounds__(256, 2) k_affA(const float* __restrict__ qk) {
    extern __shared__ char sm[];
    __nv_bfloat16* qkb = (__nv_bfloat16*)(sm + SB_QKB);
    unsigned* red = (unsigned*)(sm + SB_RED);
    const uint32_t sbase = (uint32_t)__cvta_generic_to_shared(sm);

    const int tid = threadIdx.x, lane = tid & 31, wid = tid >> 5;
    const int qw = wid >> 1, mw = wid & 1;
    const int r8 = lane >> 2, t4 = lane & 3;
    const int q0 = blockIdx.x * QT;
    const int chunk = blockIdx.y;
    const int mc0 = chunk * CHUNKP;

    STAGE_QKB();
    if (tid < QT) red[tid] = 0u;

    #pragma unroll
    for (int s = 0; s < NSTAGE - 1; s++) {
        STAGE_B_ASYNC(s, mc0 + s * MTILE);
        CP_COMMIT();
    }
    __syncthreads();

    uint32_t afr[2][4][4];
    LOAD_AFR();

    float rmax[4] = {-3.0e38f, -3.0e38f, -3.0e38f, -3.0e38f};

    for (int it = 0; it < ITERS1; it++) {
        const int s = it & (NSTAGE - 1);
        CP_WAIT2();
        __syncthreads();

        float acc[2][4][4];
        #pragma unroll
        for (int i = 0; i < 2; i++)
            #pragma unroll
            for (int j = 0; j < 4; j++)
                #pragma unroll
                for (int e = 0; e < 4; e++) acc[i][j][e] = 0.f;

        DO_MMA(s);

        if (it + NSTAGE - 1 < ITERS1) {
            STAGE_B_ASYNC((it + NSTAGE - 1) & (NSTAGE - 1), mc0 + (it + NSTAGE - 1) * MTILE);
        }
        CP_COMMIT();

        const float* nq = (const float*)(sm + SB_NASQ + s * 256);
        #pragma unroll
        for (int Mt = 0; Mt < 2; Mt++) {
            #pragma unroll
            for (int Nt = 0; Nt < 4; Nt++) {
                int ml = mw * 32 + Nt * 8 + 2 * t4;
                float2 nn = *(const float2*)&nq[ml];
                float a0 = fmaxf(0.25f * acc[Mt][Nt][0] + nn.x, 0.25f * acc[Mt][Nt][1] + nn.y);
                float a1 = fmaxf(0.25f * acc[Mt][Nt][2] + nn.x, 0.25f * acc[Mt][Nt][3] + nn.y);
                rmax[2 * Mt + 0] = fmaxf(rmax[2 * Mt + 0], a0);
                rmax[2 * Mt + 1] = fmaxf(rmax[2 * Mt + 1], a1);
            }
        }
    }

    #pragma unroll
    for (int i = 0; i < 4; i++) {
        #pragma unroll
        for (int s2 = 1; s2 <= 2; s2 <<= 1) {
            float o = __shfl_xor_sync(0xffffffffu, rmax[i], s2);
            rmax[i] = fmaxf(rmax[i], o);
        }
    }
    if (t4 == 0) {
        #pragma unroll
        for (int i = 0; i < 4; i++) {
            int row = qw * 32 + (i >> 1) * 16 + r8 + (i & 1) * 8;
            atomicMax(&red[row], encf(rmax[i]));
        }
    }
    __syncthreads();
    if (tid < QT) g_chunkmax[(q0 + tid) * NCHUNK + chunk] = red[tid];
}

// ---------------- K2: filter GEMM pass B -> collect hits (smem-buffered) -----
__global__ void __launch_bounds__(256, 2) k_affB(const float* __restrict__ qk) {
    extern __shared__ char sm[];
    __nv_bfloat16* qkb = (__nv_bfloat16*)(sm + SB_QKB);
    int* scnt = (int*)(sm + SB_SCNT);
    int* sbuf = (int*)(sm + SB_SBUF);
    const uint32_t sbase = (uint32_t)__cvta_generic_to_shared(sm);

    const int tid = threadIdx.x, lane = tid & 31, wid = tid >> 5;
    const int qw = wid >> 1, mw = wid & 1;
    const int r8 = lane >> 2, t4 = lane & 3;
    const int q0 = blockIdx.x * QT;
    const int chunk = blockIdx.y;
    const int mc0 = chunk * CHUNKP;

    STAGE_QKB();
    if (tid < QT) scnt[tid] = 0;

    #pragma unroll
    for (int s = 0; s < NSTAGE - 1; s++) {
        STAGE_B_ASYNC(s, mc0 + s * MTILE);
        CP_COMMIT();
    }

    // inline per-q thresholds (3rd-smallest encoded = 20th-largest chunk max)
    float T[4];
    int qg[4], rl[4];
    #pragma unroll
    for (int i = 0; i < 4; i++) {
        rl[i] = qw * 32 + (i >> 1) * 16 + r8 + (i & 1) * 8;
        qg[i] = q0 + rl[i];
        if (qg[i] < QD) {
            unsigned s1 = 0xFFFFFFFFu, s2 = 0xFFFFFFFFu, s3 = 0xFFFFFFFFu;
            const unsigned* cm = &g_chunkmax[qg[i] * NCHUNK];
            #pragma unroll
            for (int c = 0; c < NCHUNK; c++) {
                unsigned u = cm[c];
                if (u < s1)      { s3 = s2; s2 = s1; s1 = u; }
                else if (u < s2) { s3 = s2; s2 = u; }
                else if (u < s3) { s3 = u; }
            }
            T[i] = decf(s3) - 0.0625f;
        } else {
            T[i] = 3.4e38f;
        }
    }
    __syncthreads();

    uint32_t afr[2][4][4];
    LOAD_AFR();

    for (int it = 0; it < ITERS1; it++) {
        const int s = it & (NSTAGE - 1);
        const int m_base = mc0 + it * MTILE;
        CP_WAIT2();
        __syncthreads();

        float acc[2][4][4];
        #pragma unroll
        for (int i = 0; i < 2; i++)
            #pragma unroll
            for (int j = 0; j < 4; j++)
                #pragma unroll
                for (int e = 0; e < 4; e++) acc[i][j][e] = 0.f;

        DO_MMA(s);

        if (it + NSTAGE - 1 < ITERS1) {
            STAGE_B_ASYNC((it + NSTAGE - 1) & (NSTAGE - 1), mc0 + (it + NSTAGE - 1) * MTILE);
        }
        CP_COMMIT();

        // epilogue: warp-uniform-gated hit push into per-q smem buffers
        const float* nq = (const float*)(sm + SB_NASQ + s * 256);
        #pragma unroll
        for (int Mt = 0; Mt < 2; Mt++) {
            #pragma unroll
            for (int Nt = 0; Nt < 4; Nt++) {
                int ml = mw * 32 + Nt * 8 + 2 * t4;
                float2 nn = *(const float2*)&nq[ml];
                float v00 = 0.25f * acc[Mt][Nt][0] + nn.x;
                float v01 = 0.25f * acc[Mt][Nt][1] + nn.y;
                float v10 = 0.25f * acc[Mt][Nt][2] + nn.x;
                float v11 = 0.25f * acc[Mt][Nt][3] + nn.y;
                const int i0 = 2 * Mt, i1 = 2 * Mt + 1;
                unsigned msk = (v00 >= T[i0] ? 1u : 0u) | (v01 >= T[i0] ? 2u : 0u)
                             | (v10 >= T[i1] ? 4u : 0u) | (v11 >= T[i1] ? 8u : 0u);
                if (__any_sync(0xffffffffu, msk != 0u)) {   // warp-uniform, rarely taken
                    if (msk & 1u) {
                        int p = atomicAdd(&scnt[rl[i0]], 1);
                        if (p < CAP2) sbuf[rl[i0] * CAP2 + p] = m_base + ml;
                        else { int g = atomicAdd(&g_hcnt[qg[i0]], 1);
                               if (g < HCAP) g_hits[(size_t)qg[i0] * HCAP + g] = m_base + ml; }
                    }
                    if (msk & 2u) {
                        int p = atomicAdd(&scnt[rl[i0]], 1);
                        if (p < CAP2) sbuf[rl[i0] * CAP2 + p] = m_base + ml + 1;
                        else { int g = atomicAdd(&g_hcnt[qg[i0]], 1);
                               if (g < HCAP) g_hits[(size_t)qg[i0] * HCAP + g] = m_base + ml + 1; }
                    }
                    if (msk & 4u) {
                        int p = atomicAdd(&scnt[rl[i1]], 1);
                        if (p < CAP2) sbuf[rl[i1] * CAP2 + p] = m_base + ml;
                        else { int g = atomicAdd(&g_hcnt[qg[i1]], 1);
                               if (g < HCAP) g_hits[(size_t)qg[i1] * HCAP + g] = m_base + ml; }
                    }
                    if (msk & 8u) {
                        int p = atomicAdd(&scnt[rl[i1]], 1);
                        if (p < CAP2) sbuf[rl[i1] * CAP2 + p] = m_base + ml + 1;
                        else { int g = atomicAdd(&g_hcnt[qg[i1]], 1);
                               if (g < HCAP) g_hits[(size_t)qg[i1] * HCAP + g] = m_base + ml + 1; }
                    }
                }
            }
        }
    }

    // flush per-q smem buffers to global
    __syncthreads();
    if (tid < QT) {
        int q = q0 + tid;
        if (q < QD) {
            int n = min(scnt[tid], CAP2);
            if (n > 0) {
                int base = atomicAdd(&g_hcnt[q], n);
                for (int i = 0; i < n; i++) {
                    int p = base + i;
                    if (p < HCAP) g_hits[(size_t)q * HCAP + p] = sbuf[tid * CAP2 + i];
                }
            }
        }
    }
}

// ---------------- K3: exact fp32 eval of hits + rank-count top-20 + softmax --
__global__ void k_rescue(const float* __restrict__ qk) {
    __shared__ int   pool[8][HCAP];
    __shared__ float pval[8][HCAP];
    __shared__ float qcol[8][CKD];
    __shared__ float sval[8][TOPK];
    __shared__ int   sidx[8][TOPK];

    int w = threadIdx.x >> 5, lane = threadIdx.x & 31;
    int q = blockIdx.x * 8 + w;
    if (q >= QD) return;

    qcol[w][lane] = qk[lane * QD + q];
    qcol[w][lane + 32] = qk[(lane + 32) * QD + q];
    int cnt = g_hcnt[q];
    if (cnt > HCAP) cnt = HCAP;
    const int* hp = g_hits + (size_t)q * HCAP;
    for (int i = lane; i < cnt; i += 32) pool[w][i] = hp[i];
    __syncwarp();

    for (int i = lane; i < cnt; i += 32) {
        int m = pool[w][i];
        const float4* kr = (const float4*)(g_mktf + (size_t)m * CKD);
        float dot = 0.f;
        #pragma unroll
        for (int c4 = 0; c4 < 16; c4++) {
            float4 kv = kr[c4];
            dot += kv.x * qcol[w][c4 * 4 + 0] + kv.y * qcol[w][c4 * 4 + 1]
                 + kv.z * qcol[w][c4 * 4 + 2] + kv.w * qcol[w][c4 * 4 + 3];
        }
        pval[w][i] = 0.25f * dot + g_nasq[m];
    }
    __syncwarp();

    // rank-count selection (strict total order: val desc, idx asc) — ranks unique
    for (int i = lane; i < cnt; i += 32) {
        float vi = pval[w][i];
        int   ii = pool[w][i];
        int rank = 0;
        for (int j = 0; j < cnt; j++) {
            float vj = pval[w][j];
            int   ij = pool[w][j];
            rank += (vj > vi || (vj == vi && ij < ii)) ? 1 : 0;
        }
        if (rank < TOPK) { sval[w][rank] = vi; sidx[w][rank] = ii; }
    }
    __syncwarp();

    float v = (lane < TOPK) ? sval[w][lane] : -3.4e38f;
    float mx = v;
    #pragma unroll
    for (int s = 16; s > 0; s >>= 1) {
        float o = __shfl_xor_sync(0xffffffffu, mx, s);
        if (o > mx) mx = o;
    }
    float e = (lane < TOPK) ? expf(v - mx) : 0.f;
    float sum = e;
    #pragma unroll
    for (int s = 16; s > 0; s >>= 1) sum += __shfl_xor_sync(0xffffffffu, sum, s);
    if (lane < TOPK) {
        g_wval[q * TOPK + lane] = e / sum;
        g_widx[q * TOPK + lane] = sidx[w][lane];
    }
}

// ---------------- K4: sparse readout (fp16 v, half2 loads) -------------------
__global__ void k_readout(float* __restrict__ out) {
    __shared__ float sw[QT3 * TOPK];
    __shared__ int   si[QT3 * TOPK];
    int q0 = blockIdx.x * QT3;
    int ch2 = blockIdx.y * 256 + threadIdx.x;   // half2 index
    for (int t = threadIdx.x; t < QT3 * TOPK; t += 256) {
        int q = q0 + t / TOPK;
        if (q < QD) {
            sw[t] = g_wval[q * TOPK + (t % TOPK)];
            si[t] = g_widx[q * TOPK + (t % TOPK)];
        } else { sw[t] = 0.f; si[t] = 0; }
    }
    __syncthreads();

    const __half2* vt2 = (const __half2*)g_vth;
    float2 acc[QT3];
    #pragma unroll
    for (int j = 0; j < QT3; j++) acc[j] = make_float2(0.f, 0.f);

    #pragma unroll
    for (int k = 0; k < TOPK; k++) {
        #pragma unroll
        for (int j = 0; j < QT3; j++) {
            float w = sw[j * TOPK + k];
            int   m = si[j * TOPK + k];
            float2 f = __half22float2(vt2[(size_t)m * (CHD / 2) + ch2]);
            acc[j].x += w * f.x;
            acc[j].y += w * f.y;
        }
    }

    int ch0 = ch2 * 2;
    if (q0 + QT3 <= QD) {
        float4* o0 = (float4*)(out + (size_t)ch0 * QD + q0);
        float4* o1 = (float4*)(out + (size_t)(ch0 + 1) * QD + q0);
        #pragma unroll
        for (int jj = 0; jj < QT3 / 4; jj++) {
            o0[jj] = make_float4(acc[jj*4].x, acc[jj*4+1].x, acc[jj*4+2].x, acc[jj*4+3].x);
            o1[jj] = make_float4(acc[jj*4].y, acc[jj*4+1].y, acc[jj*4+2].y, acc[jj*4+3].y);
        }
    } else {
        #pragma unroll
        for (int j = 0; j < QT3; j++) {
            int q = q0 + j;
            if (q < QD) {
                out[(size_t)ch0 * QD + q] = acc[j].x;
                out[(size_t)(ch0 + 1) * QD + q] = acc[j].y;
            }
        }
    }
}

// ---------------- launch (fork-join: transpose overlaps filter chain) --------
extern "C" void kernel_launch(void* const* d_in, const int* in_sizes, int n_in,
                              void* d_out, int out_size) {
    const float* qk = (const float*)d_in[0];   // [64][1620]
    const float* mk = (const float*)d_in[1];   // [64][32400]
    const float* mv = (const float*)d_in[2];   // [1536][32400]
    float* out = (float*)d_out;                // [1536][1620]
    (void)in_sizes; (void)n_in; (void)out_size;

    cudaStream_t s2;
    cudaEvent_t ev0, ev2;
    cudaStreamCreateWithFlags(&s2, cudaStreamNonBlocking);
    cudaEventCreateWithFlags(&ev0, cudaEventDisableTiming);
    cudaEventCreateWithFlags(&ev2, cudaEventDisableTiming);

    // fork: side stream runs the mem_v transpose concurrently
    cudaEventRecord(ev0, 0);
    cudaStreamWaitEvent(s2, ev0, 0);
    k_transpose<<<dim3((MD + 31) / 32, CHD / 64), 256, 0, s2>>>(mv);
    cudaEventRecord(ev2, s2);

    // main chain
    k_prep<<<MPAD / 32, 256>>>(mk);

    cudaFuncSetAttribute(k_affA, cudaFuncAttributeMaxDynamicSharedMemorySize, SB_TOTAL);
    cudaFuncSetAttribute(k_affB, cudaFuncAttributeMaxDynamicSharedMemorySize, SB_TOTAL2);
    k_affA<<<dim3(NQB, NCHUNK), 256, SB_TOTAL>>>(qk);
    k_affB<<<dim3(NQB, NCHUNK), 256, SB_TOTAL2>>>(qk);
    k_rescue<<<(QD + 7) / 8, 256>>>(qk);

    // join: readout needs transpose + rescue
    cudaStreamWaitEvent(0, ev2, 0);
    k_readout<<<dim3((QD + QT3 - 1) / QT3, CHD / 512), 256>>>(out);
}